// round 14
// baseline (speedup 1.0000x reference)
#include <cuda_runtime.h>
#include <math.h>
#include <stdint.h>

#define NN   50000
#define EE   800000
#define BB   128
#define KEXP 4
#define EPSF 1e-15f
#define NB   ((NN + 255) / 256)   // 196

__constant__ float c_curv[KEXP] = {-1.0f, 0.0f, 1.0f, -0.5f};

// ---------------- scratch (device globals; no runtime allocs) ----------------
__device__ float g_dinv[NN];
__device__ int   g_degcnt[NN];
__device__ int   g_off[NN + 1];
__device__ int   g_cursor[NN];
__device__ int   g_adj[EE];
__device__ int   g_bsum[NB];
__device__ int   g_boff[NB];
__device__ float g_xm[(size_t)KEXP * NN * 128];
__device__ float g_t [(size_t)KEXP * NN * 128];
__device__ float g_xn[(size_t)KEXP * NN];
__device__ float g_s0[(size_t)KEXP * NN];
__device__ float g_gm1[NN * 32];
__device__ float g_g1 [NN * 32];
__device__ float g_gm2[NN * 128];
__device__ float g_gt [NN * 128];
__device__ float g_feat[BB * 512];
__device__ float g_hgate[BB * 128];
__device__ float g_biaspt[2 * KEXP * 128];   // [layer][expert][128]
__device__ float g_bp2[2 * KEXP];

// ---------------- math helpers (all fp32) ----------------
__device__ __forceinline__ float tan_k(float x, float k) {
    if (k > 0.f) { float sk = sqrtf(k);  return tanf(x * sk) / sk; }
    if (k < 0.f) { float sk = sqrtf(-k); return tanhf(x * sk) / sk; }
    return x;
}
__device__ __forceinline__ float artan_k(float x, float k) {
    if (k > 0.f) { float sk = sqrtf(k);  return atanf(x * sk) / sk; }
    if (k < 0.f) {
        float sk = sqrtf(-k);
        float z = fminf(fmaxf(x * sk, -1.0f + 1e-7f), 1.0f - 1e-7f);
        return atanhf(z) / sk;
    }
    return x;
}
__device__ __forceinline__ float warp_sum(float v) {
#pragma unroll
    for (int o = 16; o; o >>= 1) v += __shfl_xor_sync(0xffffffffu, v, o);
    return v;
}
__device__ __forceinline__ float vnorm_w(const float* v) {
    float s = v[0]*v[0] + v[1]*v[1] + v[2]*v[2] + v[3]*v[3];
    return fmaxf(sqrtf(warp_sum(s)), EPSF);
}
__device__ __forceinline__ void project_w(float* v, float k) {
    if (k >= 0.f) return;
    float n = vnorm_w(v);
    float maxn = (1.0f - 1e-5f) * rsqrtf(-k);
    if (n > maxn) {
        float f = maxn / n;
#pragma unroll
        for (int c = 0; c < 4; c++) v[c] *= f;
    }
}
__device__ __forceinline__ void expmap0_w(float* v, float k) {
    float n = vnorm_w(v);
    float s = tan_k(n, k) / n;
#pragma unroll
    for (int c = 0; c < 4; c++) v[c] *= s;
    project_w(v, k);
}
__device__ __forceinline__ void logmap0_w(float* v, float k) {
    float n = vnorm_w(v);
    float s = artan_k(n, k) / n;
#pragma unroll
    for (int c = 0; c < 4; c++) v[c] *= s;
}
__device__ __forceinline__ int lower_bound_batch(const int* __restrict__ b, int val) {
    int lo = 0, hi = NN;
    while (lo < hi) { int mid = (lo + hi) >> 1; if (b[mid] < val) lo = mid + 1; else hi = mid; }
    return lo;
}
__device__ __forceinline__ float bred128(float v, float* sh) {
    v = warp_sum(v);
    int w = threadIdx.x >> 5;
    if ((threadIdx.x & 31) == 0) sh[w] = v;
    __syncthreads();
    float r = sh[0] + sh[1] + sh[2] + sh[3];
    __syncthreads();
    return r;
}

// ---------------- graph prep ----------------
__global__ void k_prep0() {
    int i = blockIdx.x * blockDim.x + threadIdx.x;
    if (i < NN) { g_degcnt[i] = 0; g_cursor[i] = 0; }
}
__global__ void k_deg(const int* __restrict__ col) {
    int e = blockIdx.x * blockDim.x + threadIdx.x;
    if (e < EE) atomicAdd(&g_degcnt[col[e]], 1);
}
__global__ void k_dinvsum() {
    __shared__ int sh[256];
    int t = threadIdx.x;
    int i = blockIdx.x * 256 + t;
    int v = (i < NN) ? g_degcnt[i] : 0;
    if (i < NN) g_dinv[i] = rsqrtf((float)(v + 1));
    sh[t] = v;
    __syncthreads();
#pragma unroll
    for (int o = 128; o; o >>= 1) {
        if (t < o) sh[t] += sh[t + o];
        __syncthreads();
    }
    if (t == 0) g_bsum[blockIdx.x] = sh[0];
}
__global__ void k_scanb() {
    __shared__ int s[256];
    int t = threadIdx.x;
    int v = (t < NB) ? g_bsum[t] : 0;
    s[t] = v;
    __syncthreads();
#pragma unroll
    for (int o = 1; o < 256; o <<= 1) {
        int x = (t >= o) ? s[t - o] : 0;
        __syncthreads();
        s[t] += x;
        __syncthreads();
    }
    if (t < NB) g_boff[t] = s[t] - v;
    if (t == 255) g_off[NN] = s[255];
}
__global__ void k_off() {
    __shared__ int s[256];
    int t = threadIdx.x;
    int i = blockIdx.x * 256 + t;
    int v = (i < NN) ? g_degcnt[i] : 0;
    s[t] = v;
    __syncthreads();
#pragma unroll
    for (int o = 1; o < 256; o <<= 1) {
        int x = (t >= o) ? s[t - o] : 0;
        __syncthreads();
        s[t] += x;
        __syncthreads();
    }
    if (i < NN) g_off[i] = g_boff[blockIdx.x] + s[t] - v;
}
__global__ void k_adj(const int* __restrict__ row, const int* __restrict__ col) {
    int e = blockIdx.x * blockDim.x + threadIdx.x;
    if (e < EE) {
        int d = col[e];
        int p = g_off[d] + atomicAdd(&g_cursor[d], 1);
        g_adj[p] = row[e];
    }
}

// ---------------- layer-0 prep ----------------
__global__ void k_norm0(const float* __restrict__ x) {
    int node = blockIdx.x * 8 + (threadIdx.x >> 5);
    if (node >= NN) return;
    int lane = threadIdx.x & 31;
    float4 xv = ((const float4*)(x + (size_t)node * 128))[lane];
    float s2 = xv.x*xv.x + xv.y*xv.y + xv.z*xv.z + xv.w*xv.w;
    float n = fmaxf(sqrtf(warp_sum(s2)), EPSF);
    if (lane == 0) {
#pragma unroll
        for (int e = 0; e < KEXP; e++) {
            float k = c_curv[e];
            float tk = tan_k(n, k);
            float s = tk / n;
            float vn = fabsf(tk);
            if (k < 0.f) {
                float maxn = (1.0f - 1e-5f) * rsqrtf(-k);
                if (vn > maxn) { s *= maxn / vn; vn = maxn; }
            }
            g_s0[(size_t)e * NN + node] = s;
            g_xn[(size_t)e * NN + node] = fmaxf(vn, EPSF);
        }
    }
}

__global__ void k_bias_all(const float* __restrict__ bsrc, int layer) { // grid=KEXP
    __shared__ float sh[4];
    int e = blockIdx.x;
    float k = c_curv[e];
    int t = threadIdx.x;
    float v = bsrc[e * 128 + t];
    float n2 = bred128(v * v, sh);
    float n = fmaxf(sqrtf(n2), EPSF);
    float p = (tan_k(n, k) / n) * v;
    if (k < 0.f) {
        float p2 = bred128(p * p, sh);
        float pn = fmaxf(sqrtf(p2), EPSF);
        float maxn = (1.0f - 1e-5f) * rsqrtf(-k);
        if (pn > maxn) p *= maxn / pn;
    }
    float p2f = bred128(p * p, sh);
    g_biaspt[(layer * KEXP + e) * 128 + t] = p;
    if (t == 0) g_bp2[layer * KEXP + e] = p2f;
}

// gather-aggregate (CSR) + expmap0 [+ fused logmap0 final layer]: g_t[e] -> g_xm[e]
__global__ void k_agg(int e, float k, int fuseLog) {
    int d = blockIdx.x * 8 + (threadIdx.x >> 5);
    if (d >= NN) return;
    int lane = threadIdx.x & 31;
    const float* __restrict__ t = g_t + (size_t)e * NN * 128;
    float dd = g_dinv[d];
    float4 sv4 = ((const float4*)(t + (size_t)d * 128))[lane];
    float sw = dd * dd;
    float a0 = sw * sv4.x, a1 = sw * sv4.y, a2 = sw * sv4.z, a3 = sw * sv4.w;
    int p0 = g_off[d], p1 = g_off[d + 1];
    for (int p = p0; p < p1; p += 32) {
        int cnt = min(32, p1 - p);
        int sidx = 0; float wv = 0.f;
        if (p + lane < p1) { sidx = g_adj[p + lane]; wv = dd * g_dinv[sidx]; }
        int q = 0;
        for (; q + 4 <= cnt; q += 4) {
            int s0 = __shfl_sync(0xffffffffu, sidx, q);
            int s1 = __shfl_sync(0xffffffffu, sidx, q + 1);
            int s2 = __shfl_sync(0xffffffffu, sidx, q + 2);
            int s3 = __shfl_sync(0xffffffffu, sidx, q + 3);
            float w0 = __shfl_sync(0xffffffffu, wv, q);
            float w1 = __shfl_sync(0xffffffffu, wv, q + 1);
            float w2 = __shfl_sync(0xffffffffu, wv, q + 2);
            float w3 = __shfl_sync(0xffffffffu, wv, q + 3);
            float4 n0 = ((const float4*)(t + (size_t)s0 * 128))[lane];
            float4 n1 = ((const float4*)(t + (size_t)s1 * 128))[lane];
            float4 n2 = ((const float4*)(t + (size_t)s2 * 128))[lane];
            float4 n3 = ((const float4*)(t + (size_t)s3 * 128))[lane];
            a0 = fmaf(w0, n0.x, a0); a1 = fmaf(w0, n0.y, a1);
            a2 = fmaf(w0, n0.z, a2); a3 = fmaf(w0, n0.w, a3);
            a0 = fmaf(w1, n1.x, a0); a1 = fmaf(w1, n1.y, a1);
            a2 = fmaf(w1, n1.z, a2); a3 = fmaf(w1, n1.w, a3);
            a0 = fmaf(w2, n2.x, a0); a1 = fmaf(w2, n2.y, a1);
            a2 = fmaf(w2, n2.z, a2); a3 = fmaf(w2, n2.w, a3);
            a0 = fmaf(w3, n3.x, a0); a1 = fmaf(w3, n3.y, a1);
            a2 = fmaf(w3, n3.z, a2); a3 = fmaf(w3, n3.w, a3);
        }
        for (; q < cnt; q++) {
            int   s = __shfl_sync(0xffffffffu, sidx, q);
            float w = __shfl_sync(0xffffffffu, wv, q);
            float4 nv = ((const float4*)(t + (size_t)s * 128))[lane];
            a0 = fmaf(w, nv.x, a0); a1 = fmaf(w, nv.y, a1);
            a2 = fmaf(w, nv.z, a2); a3 = fmaf(w, nv.w, a3);
        }
    }
    float v[4] = {a0, a1, a2, a3};
    expmap0_w(v, k);
    if (fuseLog) {
        logmap0_w(v, k);
    } else {
        float nv = vnorm_w(v);
        if (lane == 0) g_xn[(size_t)e * NN + d] = nv;
    }
    ((float4*)(g_xm + ((size_t)e * NN + d) * 128))[lane] = make_float4(v[0], v[1], v[2], v[3]);
}

// ---------------- GEMM (+ fused Mobius point epilogue) ----------------
template<int KD, int MODE>
__global__ void gemmf(const float* __restrict__ Xin, const float* __restrict__ W0,
                      int wOfs, int n, int eBase) {
    const float* __restrict__ A;
    float* __restrict__ OUT;
    int lda;
    int eIdx = eBase + blockIdx.y;
    if (MODE == 0) {
        A = Xin; OUT = g_t + (size_t)eIdx * NN * 128; lda = 128;
    } else if (MODE == 1) {
        size_t eo = (size_t)eIdx * NN * 128;
        A = g_xm + eo; OUT = g_t + eo; lda = 128;
    } else {
        A = g_g1; OUT = g_gm2; lda = 32;
    }
    const float* __restrict__ W = W0 + (size_t)eIdx * wOfs;
    __shared__ __align__(16) float As[32][132];
    __shared__ __align__(16) float Bs[32][132];
    __shared__ float red2[128][17];
    __shared__ float redd[128][17];
    __shared__ float reda[128][17];
    __shared__ float2 abArr[128];
    int tid = threadIdx.x;
    int tx = tid & 15, ty = tid >> 4;
    int node0 = blockIdx.x * 128;

    const int bofs = (MODE == 0) ? 0 : KEXP;
    float bpv[8];
    if (MODE < 2) {
        float4 b0 = *(const float4*)(g_biaspt + (bofs + eIdx) * 128 + tx * 4);
        float4 b1 = *(const float4*)(g_biaspt + (bofs + eIdx) * 128 + 64 + tx * 4);
        bpv[0]=b0.x; bpv[1]=b0.y; bpv[2]=b0.z; bpv[3]=b0.w;
        bpv[4]=b1.x; bpv[5]=b1.y; bpv[6]=b1.z; bpv[7]=b1.w;
    }

    float acc[8][8];
#pragma unroll
    for (int m = 0; m < 8; m++)
#pragma unroll
        for (int j = 0; j < 8; j++) acc[m][j] = 0.f;

    for (int k0 = 0; k0 < KD; k0 += 32) {
#pragma unroll
        for (int r = 0; r < 4; r++) {
            int m  = (tid >> 3) + r * 32;
            int kk = (tid & 7) * 4;
            float4 va = make_float4(0.f, 0.f, 0.f, 0.f);
            if (node0 + m < n)
                va = *(const float4*)(A + (size_t)(node0 + m) * lda + k0 + kk);
            As[kk + 0][m] = va.x; As[kk + 1][m] = va.y; As[kk + 2][m] = va.z; As[kk + 3][m] = va.w;
            float4 vb = *(const float4*)(W + (size_t)m * KD + k0 + kk);
            Bs[kk + 0][m] = vb.x; Bs[kk + 1][m] = vb.y; Bs[kk + 2][m] = vb.z; Bs[kk + 3][m] = vb.w;
        }
        __syncthreads();
#pragma unroll
        for (int kk = 0; kk < 32; kk++) {
            float4 a0 = *(const float4*)&As[kk][ty * 4];
            float4 a1 = *(const float4*)&As[kk][64 + ty * 4];
            float4 b0 = *(const float4*)&Bs[kk][tx * 4];
            float4 b1 = *(const float4*)&Bs[kk][64 + tx * 4];
            float a[8] = {a0.x, a0.y, a0.z, a0.w, a1.x, a1.y, a1.z, a1.w};
            float b[8] = {b0.x, b0.y, b0.z, b0.w, b1.x, b1.y, b1.z, b1.w};
#pragma unroll
            for (int m = 0; m < 8; m++)
#pragma unroll
                for (int j = 0; j < 8; j++) acc[m][j] = fmaf(a[m], b[j], acc[m][j]);
        }
        __syncthreads();
    }

    if (MODE == 2) {
#pragma unroll
        for (int m = 0; m < 8; m++) {
            int row = node0 + ((m < 4) ? (ty * 4 + m) : (64 + ty * 4 + m - 4));
            if (row < n) {
                *(float4*)(OUT + (size_t)row * 128 + tx * 4) =
                    make_float4(acc[m][0], acc[m][1], acc[m][2], acc[m][3]);
                *(float4*)(OUT + (size_t)row * 128 + 64 + tx * 4) =
                    make_float4(acc[m][4], acc[m][5], acc[m][6], acc[m][7]);
            }
        }
        return;
    }

    float kv = c_curv[eIdx];
#pragma unroll
    for (int m = 0; m < 8; m++) {
        int rloc = (m < 4) ? (ty * 4 + m) : (64 + ty * 4 + m - 4);
        float s2 = 0.f, sd = 0.f, sa = 0.f;
#pragma unroll
        for (int j = 0; j < 8; j++) {
            float v = acc[m][j];
            s2 = fmaf(v, v, s2); sd = fmaf(v, bpv[j], sd); sa += fabsf(v);
        }
        red2[rloc][tx] = s2; redd[rloc][tx] = sd; reda[rloc][tx] = sa;
    }
    __syncthreads();
    if (tid < 128) {
        int node = node0 + tid;
        if (node < n) {
            float S2 = 0.f, SD = 0.f, SA = 0.f;
#pragma unroll
            for (int i = 0; i < 16; i++) {
                S2 += red2[tid][i]; SD += redd[tid][i]; SA += reda[tid][i];
            }
            float c = 1.f;
            if (MODE == 0) c = g_s0[(size_t)eIdx * NN + node];
            S2 *= c * c; SD *= c; SA *= fabsf(c);
            float alpha, beta;
            if (kv == 0.f) {
                alpha = 1.f; beta = 1.f;
            } else {
                float bp2 = g_bp2[bofs + eIdx];
                float mxn = fmaxf(sqrtf(S2), EPSF);
                float xn  = g_xn[(size_t)eIdx * NN + node];
                float s1 = tan_k(mxn / xn * artan_k(xn, kv), kv) / mxn;
                if (SA == 0.f) s1 = 0.f;
                if (kv < 0.f) {
                    float maxn = (1.0f - 1e-5f) * rsqrtf(-kv);
                    float hn = fmaxf(fabsf(s1) * mxn, EPSF);
                    if (hn > maxn) s1 *= maxn / hn;
                }
                float h2 = s1 * s1 * S2;
                float xy = s1 * SD;
                float num_h = 1.f - 2.f * kv * xy - kv * bp2;
                float num_b = 1.f + kv * h2;
                float den = fmaxf(1.f - 2.f * kv * xy + kv * kv * h2 * bp2, 1e-15f);
                float a1f = num_h * s1 / den;
                float b1f = num_b / den;
                float an2 = fmaxf(a1f * a1f * S2 + 2.f * a1f * b1f * SD + b1f * b1f * bp2, 0.f);
                float an = fmaxf(sqrtf(an2), EPSF);
                float cf2 = 1.f;
                if (kv < 0.f) {
                    float maxn = (1.0f - 1e-5f) * rsqrtf(-kv);
                    if (an > maxn) cf2 = maxn / an;
                }
                float np = fmaxf(an * cf2, EPSF);
                float lg = artan_k(np, kv) / np;
                alpha = lg * cf2 * a1f;
                beta  = lg * cf2 * b1f;
            }
            abArr[tid] = make_float2(alpha * c, beta);
        }
    }
    __syncthreads();
#pragma unroll
    for (int m = 0; m < 8; m++) {
        int rloc = (m < 4) ? (ty * 4 + m) : (64 + ty * 4 + m - 4);
        int row = node0 + rloc;
        if (row < n) {
            float2 ab = abArr[rloc];
            float o[8];
#pragma unroll
            for (int j = 0; j < 8; j++) o[j] = fmaf(ab.x, acc[m][j], ab.y * bpv[j]);
            *(float4*)(OUT + (size_t)row * 128 + tx * 4) =
                make_float4(o[0], o[1], o[2], o[3]);
            *(float4*)(OUT + (size_t)row * 128 + 64 + tx * 4) =
                make_float4(o[4], o[5], o[6], o[7]);
        }
    }
}

// ---------------- gate ----------------
__global__ void k_gate1(const float* __restrict__ x, const float* __restrict__ gw1) {
    __shared__ float wT[128 * 33];
    int tid = threadIdx.x;
    for (int l = tid; l < 4096; l += 256) {
        int j = l >> 7, i = l & 127;
        wT[i * 33 + j] = gw1[l];
    }
    __syncthreads();
    int warp = tid >> 5, lane = tid & 31;
    for (int rep = 0; rep < 4; rep++) {
        int node = blockIdx.x * 32 + rep * 8 + warp;
        if (node < NN) {
            float xv[4];
#pragma unroll
            for (int c = 0; c < 4; c++) xv[c] = x[node * 128 + c * 32 + lane];
            float accv = 0.f;
#pragma unroll
            for (int i = 0; i < 128; i++) {
                float xi = __shfl_sync(0xffffffffu, xv[i >> 5], i & 31);
                accv = fmaf(xi, wT[i * 33 + lane], accv);
            }
            g_gm1[node * 32 + lane] = accv;
        }
    }
}
__global__ void k_gagg1(const float* __restrict__ gb1) {
    int d = blockIdx.x * 8 + (threadIdx.x >> 5);
    if (d >= NN) return;
    int lane = threadIdx.x & 31;
    float dd = g_dinv[d];
    float acc = dd * dd * g_gm1[d * 32 + lane];
    int p0 = g_off[d], p1 = g_off[d + 1];
    for (int p = p0; p < p1; p += 32) {
        int cnt = min(32, p1 - p);
        int sidx = 0; float wv = 0.f;
        if (p + lane < p1) { sidx = g_adj[p + lane]; wv = dd * g_dinv[sidx]; }
        for (int q = 0; q < cnt; q++) {
            int   s = __shfl_sync(0xffffffffu, sidx, q);
            float w = __shfl_sync(0xffffffffu, wv, q);
            acc += w * g_gm1[s * 32 + lane];
        }
    }
    g_g1[d * 32 + lane] = fmaxf(acc + gb1[lane], 0.f);
}
__global__ void k_gagg2(const float* __restrict__ gb2) {
    int d = blockIdx.x * 8 + (threadIdx.x >> 5);
    if (d >= NN) return;
    int lane = threadIdx.x & 31;
    float dd = g_dinv[d];
    float4 sv4 = ((const float4*)(g_gm2 + (size_t)d * 128))[lane];
    float sw = dd * dd;
    float a0 = sw * sv4.x, a1 = sw * sv4.y, a2 = sw * sv4.z, a3 = sw * sv4.w;
    int p0 = g_off[d], p1 = g_off[d + 1];
    for (int p = p0; p < p1; p += 32) {
        int cnt = min(32, p1 - p);
        int sidx = 0; float wv = 0.f;
        if (p + lane < p1) { sidx = g_adj[p + lane]; wv = dd * g_dinv[sidx]; }
        int q = 0;
        for (; q + 4 <= cnt; q += 4) {
            int s0 = __shfl_sync(0xffffffffu, sidx, q);
            int s1 = __shfl_sync(0xffffffffu, sidx, q + 1);
            int s2 = __shfl_sync(0xffffffffu, sidx, q + 2);
            int s3 = __shfl_sync(0xffffffffu, sidx, q + 3);
            float w0 = __shfl_sync(0xffffffffu, wv, q);
            float w1 = __shfl_sync(0xffffffffu, wv, q + 1);
            float w2 = __shfl_sync(0xffffffffu, wv, q + 2);
            float w3 = __shfl_sync(0xffffffffu, wv, q + 3);
            float4 n0 = ((const float4*)(g_gm2 + (size_t)s0 * 128))[lane];
            float4 n1 = ((const float4*)(g_gm2 + (size_t)s1 * 128))[lane];
            float4 n2 = ((const float4*)(g_gm2 + (size_t)s2 * 128))[lane];
            float4 n3 = ((const float4*)(g_gm2 + (size_t)s3 * 128))[lane];
            a0 = fmaf(w0, n0.x, a0); a1 = fmaf(w0, n0.y, a1);
            a2 = fmaf(w0, n0.z, a2); a3 = fmaf(w0, n0.w, a3);
            a0 = fmaf(w1, n1.x, a0); a1 = fmaf(w1, n1.y, a1);
            a2 = fmaf(w1, n1.z, a2); a3 = fmaf(w1, n1.w, a3);
            a0 = fmaf(w2, n2.x, a0); a1 = fmaf(w2, n2.y, a1);
            a2 = fmaf(w2, n2.z, a2); a3 = fmaf(w2, n2.w, a3);
            a0 = fmaf(w3, n3.x, a0); a1 = fmaf(w3, n3.y, a1);
            a2 = fmaf(w3, n3.z, a2); a3 = fmaf(w3, n3.w, a3);
        }
        for (; q < cnt; q++) {
            int   s = __shfl_sync(0xffffffffu, sidx, q);
            float w = __shfl_sync(0xffffffffu, wv, q);
            float4 nv = ((const float4*)(g_gm2 + (size_t)s * 128))[lane];
            a0 = fmaf(w, nv.x, a0); a1 = fmaf(w, nv.y, a1);
            a2 = fmaf(w, nv.z, a2); a3 = fmaf(w, nv.w, a3);
        }
    }
    float4 bv = ((const float4*)gb2)[lane];
    ((float4*)(g_gt + (size_t)d * 128))[lane] = make_float4(
        fmaxf(a0 + bv.x, 0.f), fmaxf(a1 + bv.y, 0.f),
        fmaxf(a2 + bv.z, 0.f), fmaxf(a3 + bv.w, 0.f));
}

// ---------------- pooling ----------------
__global__ void k_pool2(int sel, const int* __restrict__ batch) {
    int b = blockIdx.x, e = blockIdx.y, j = threadIdx.x;
    const float* __restrict__ src = (sel == 0) ? (g_xm + (size_t)e * NN * 128) : g_gt;
    int s = lower_bound_batch(batch, b);
    int ee = lower_bound_batch(batch, b + 1);
    float a0 = 0.f, a1 = 0.f, a2 = 0.f, a3 = 0.f;
    int nd = s;
    for (; nd + 4 <= ee; nd += 4) {
        a0 += src[(size_t)(nd + 0) * 128 + j];
        a1 += src[(size_t)(nd + 1) * 128 + j];
        a2 += src[(size_t)(nd + 2) * 128 + j];
        a3 += src[(size_t)(nd + 3) * 128 + j];
    }
    for (; nd < ee; ++nd) a0 += src[(size_t)nd * 128 + j];
    float sum = (a0 + a1) + (a2 + a3);
    if (sel == 0) g_feat[b * 512 + e * 128 + j] = sum;
    else          g_hgate[b * 128 + j] = sum;
}

// ---------------- finalize ----------------
__global__ void k_finalize(const float* __restrict__ gate_u, const float* __restrict__ tau_raw,
                           float* __restrict__ out, int out_size, const int* __restrict__ batch) {
    __shared__ float sh[4];
    int b = blockIdx.x, j = threadIdx.x;
    int s = lower_bound_batch(batch, b);
    int e = lower_bound_batch(batch, b + 1);
    float c = fmaxf((float)(e - s), 1.0f);
    float hg = g_hgate[b * 128 + j] / c;
    float hn2 = bred128(hg * hg, sh);
    const float curv[4] = {-1.0f, 0.0f, 1.0f, -0.5f};
    float dv[4], tauv[4];
    for (int i = 0; i < 4; i++) {
        float k = curv[i];
        float zn = fmaxf(sqrtf(hn2), EPSF);
        float zk = (tan_k(zn, k) / zn) * hg;
        if (k < 0.f) {
            float z2 = bred128(zk * zk, sh);
            float n = fmaxf(sqrtf(z2), EPSF);
            float maxn = (1.0f - 1e-5f) * rsqrtf(-k);
            if (n > maxn) zk *= maxn / n;
        }
        float u = gate_u[i * 128 + j];
        float un2 = bred128(u * u, sh);
        float un = fmaxf(sqrtf(un2), EPSF);
        float yk = (tan_k(un, k) / un) * u;
        if (k < 0.f) {
            float y2p = bred128(yk * yk, sh);
            float n = fmaxf(sqrtf(y2p), EPSF);
            float maxn = (1.0f - 1e-5f) * rsqrtf(-k);
            if (n > maxn) yk *= maxn / n;
        }
        float xe = -zk;
        float x2 = bred128(xe * xe, sh);
        float y2 = bred128(yk * yk, sh);
        float xy = bred128(xe * yk, sh);
        float nh = 1.f - 2.f * k * xy - k * y2;
        float nb = 1.f + k * x2;
        float den = fmaxf(1.f - 2.f * k * xy + k * k * x2 * y2, 1e-15f);
        float m = (nh * xe + nb * yk) / den;
        if (k < 0.f) {
            float m2p = bred128(m * m, sh);
            float n = fmaxf(sqrtf(m2p), EPSF);
            float maxn = (1.0f - 1e-5f) * rsqrtf(-k);
            if (n > maxn) m *= maxn / n;
        }
        float m2 = bred128(m * m, sh);
        dv[i] = 2.0f * artan_k(fmaxf(sqrtf(m2), EPSF), k);
        float tr = tau_raw[i];
        float sp = (tr > 20.f) ? tr : log1pf(expf(tr));
        tauv[i] = fminf(fmaxf(sp + 0.05f, 0.05f), 10.0f);
    }
    float l[4], mxl = -1e30f;
#pragma unroll
    for (int i = 0; i < 4; i++) { l[i] = -dv[i] / tauv[i]; mxl = fmaxf(mxl, l[i]); }
    float sum = 0.f;
#pragma unroll
    for (int i = 0; i < 4; i++) { l[i] = expf(l[i] - mxl); sum += l[i]; }
    float w[4];
#pragma unroll
    for (int i = 0; i < 4; i++) w[i] = l[i] / sum;
#pragma unroll
    for (int i = 0; i < 4; i++) {
        int idx = b * 512 + i * 128 + j;
        out[idx] = (g_feat[idx] / c) * w[i];
    }
    if (out_size >= 66564) {
        if (j < 4) {
            out[65536 + b * 4 + j] = w[j];
            out[66048 + b * 4 + j] = dv[j];
            if (b == 0) out[66560 + j] = tauv[j];
        }
    }
}

// ---------------- launch: priority-scheduled pipeline ----------------
// s1 (greatest priority): agg chain + expert pool  -- the critical path
// s4 (least priority):    per-expert layer-1 GEMMs -- scavenge idle fma slots
// s2 (default priority):  graph prep + gate path   -- hides under gemmL0
// stream 0:               head + monolithic gemmL0 + finalize
extern "C" void kernel_launch(void* const* d_in, const int* in_sizes, int n_in,
                              void* d_out, int out_size) {
    const float* x     = (const float*)d_in[0];
    const int*   ei    = (const int*)d_in[1];
    const int*   row   = ei;
    const int*   col   = ei + EE;
    const int*   batch = (const int*)d_in[2];
    const float* ew1   = (const float*)d_in[3];
    const float* eb1   = (const float*)d_in[4];
    const float* ew2   = (const float*)d_in[5];
    const float* eb2   = (const float*)d_in[6];
    const float* gw1   = (const float*)d_in[7];
    const float* gb1   = (const float*)d_in[8];
    const float* gw2   = (const float*)d_in[9];
    const float* gb2   = (const float*)d_in[10];
    const float* gu    = (const float*)d_in[11];
    const float* traw  = (const float*)d_in[12];
    float* out = (float*)d_out;

    const float curv[4] = {-1.0f, 0.0f, 1.0f, -0.5f};

    const int WG = (NN + 7) / 8;
    const int GG = (NN + 127) / 128;

    static cudaStream_t s1 = nullptr, s2 = nullptr, s4 = nullptr;
    static cudaEvent_t evFork, evL0, evPrep, evGate, evS1;
    static cudaEvent_t evA0[KEXP], evG1[KEXP];
    if (!s1) {
        int loPrio = 0, hiPrio = 0;  // loPrio = least, hiPrio = greatest (numerically smallest)
        cudaDeviceGetStreamPriorityRange(&loPrio, &hiPrio);
        cudaStreamCreateWithPriority(&s1, cudaStreamNonBlocking, hiPrio);  // aggs: highest
        cudaStreamCreateWithPriority(&s2, cudaStreamNonBlocking, 0);       // prep+gate
        cudaStreamCreateWithPriority(&s4, cudaStreamNonBlocking, loPrio);  // L1 gemms: lowest
        cudaEventCreateWithFlags(&evFork, cudaEventDisableTiming);
        cudaEventCreateWithFlags(&evL0, cudaEventDisableTiming);
        cudaEventCreateWithFlags(&evPrep, cudaEventDisableTiming);
        cudaEventCreateWithFlags(&evGate, cudaEventDisableTiming);
        cudaEventCreateWithFlags(&evS1, cudaEventDisableTiming);
        for (int e = 0; e < KEXP; e++) {
            cudaEventCreateWithFlags(&evA0[e], cudaEventDisableTiming);
            cudaEventCreateWithFlags(&evG1[e], cudaEventDisableTiming);
        }
    }

    cudaEventRecord(evFork, 0);
    cudaStreamWaitEvent(s1, evFork, 0);
    cudaStreamWaitEvent(s2, evFork, 0);
    cudaStreamWaitEvent(s4, evFork, 0);

    // stream 0 head: bias0 + norm0, then the monolithic layer-0 GEMM (launch 4)
    k_bias_all<<<KEXP, 128>>>(eb1, 0);                              // launch 1
    k_norm0<<<WG, 256>>>(x);                                        // launch 2
    k_bias_all<<<KEXP, 128, 0, s4>>>(eb2, 1);                       // launch 3 (s4)
    gemmf<128, 0><<<dim3(GG, KEXP), 256>>>(x, ew1, 16384, NN, 0);   // launch 4
    cudaEventRecord(evL0, 0);

    // s2: graph prep chain, then gate path (scavenges under gemmL0)
    k_prep0<<<(NN + 255) / 256, 256, 0, s2>>>();
    k_deg<<<(EE + 255) / 256, 256, 0, s2>>>(col);
    k_dinvsum<<<NB, 256, 0, s2>>>();
    k_scanb<<<1, 256, 0, s2>>>();
    k_off<<<NB, 256, 0, s2>>>();
    k_adj<<<(EE + 255) / 256, 256, 0, s2>>>(row, col);
    cudaEventRecord(evPrep, s2);
    k_gate1<<<(NN + 31) / 32, 256, 0, s2>>>(x, gw1);
    k_gagg1<<<WG, 256, 0, s2>>>(gb1);
    gemmf<32, 2><<<dim3(GG, 1), 256, 0, s2>>>(nullptr, gw2, 0, NN, 0);
    k_gagg2<<<WG, 256, 0, s2>>>(gb2);
    k_pool2<<<dim3(BB, 1), 128, 0, s2>>>(1, batch);
    cudaEventRecord(evGate, s2);

    // s1 (high priority): the agg critical path
    cudaStreamWaitEvent(s1, evPrep, 0);
    cudaStreamWaitEvent(s1, evL0, 0);
    for (int e = 0; e < KEXP; e++) {
        k_agg<<<WG, 256, 0, s1>>>(e, curv[e], 0);
        cudaEventRecord(evA0[e], s1);
        cudaStreamWaitEvent(s4, evA0[e], 0);
        gemmf<128, 1><<<dim3(GG, 1), 256, 0, s4>>>(nullptr, ew2, 16384, NN, e);
        cudaEventRecord(evG1[e], s4);
    }
    for (int e = 0; e < KEXP; e++) {
        cudaStreamWaitEvent(s1, evG1[e], 0);
        k_agg<<<WG, 256, 0, s1>>>(e, curv[e], 1);
    }
    k_pool2<<<dim3(BB, KEXP), 128, 0, s1>>>(0, batch);
    cudaEventRecord(evS1, s1);

    // stream 0: join everything, finalize
    cudaStreamWaitEvent(0, evS1, 0);
    cudaStreamWaitEvent(0, evGate, 0);
    k_finalize<<<BB, 128>>>(gu, traw, out, out_size, batch);
}

// round 15
// speedup vs baseline: 1.2842x; 1.2842x over previous
#include <cuda_runtime.h>
#include <math.h>
#include <stdint.h>

#define NN   50000
#define EE   800000
#define BB   128
#define KEXP 4
#define EPSF 1e-15f
#define NB   ((NN + 255) / 256)   // 196

__constant__ float c_curv[KEXP] = {-1.0f, 0.0f, 1.0f, -0.5f};

// ---------------- scratch (device globals; no runtime allocs) ----------------
__device__ float g_dinv[NN];
__device__ int   g_degcnt[NN];
__device__ int   g_off[NN + 1];
__device__ int   g_cursor[NN];
__device__ int   g_adj[EE];
__device__ int   g_bsum[NB];
__device__ int   g_boff[NB];
__device__ float g_xm[(size_t)KEXP * NN * 128];
__device__ float g_t [(size_t)KEXP * NN * 128];
__device__ float g_xn[(size_t)KEXP * NN];
__device__ float g_s0[(size_t)KEXP * NN];
__device__ float g_gm1[NN * 32];
__device__ float g_g1 [NN * 32];
__device__ float g_gm2[NN * 128];
__device__ float g_gt [NN * 128];
__device__ float g_feat[BB * 512];
__device__ float g_hgate[BB * 128];
__device__ float g_biaspt[2 * KEXP * 128];   // [layer][expert][128]
__device__ float g_bp2[2 * KEXP];

// ---------------- math helpers (all fp32) ----------------
__device__ __forceinline__ float tan_k(float x, float k) {
    if (k > 0.f) { float sk = sqrtf(k);  return tanf(x * sk) / sk; }
    if (k < 0.f) { float sk = sqrtf(-k); return tanhf(x * sk) / sk; }
    return x;
}
__device__ __forceinline__ float artan_k(float x, float k) {
    if (k > 0.f) { float sk = sqrtf(k);  return atanf(x * sk) / sk; }
    if (k < 0.f) {
        float sk = sqrtf(-k);
        float z = fminf(fmaxf(x * sk, -1.0f + 1e-7f), 1.0f - 1e-7f);
        return atanhf(z) / sk;
    }
    return x;
}
__device__ __forceinline__ float warp_sum(float v) {
#pragma unroll
    for (int o = 16; o; o >>= 1) v += __shfl_xor_sync(0xffffffffu, v, o);
    return v;
}
__device__ __forceinline__ float vnorm_w(const float* v) {
    float s = v[0]*v[0] + v[1]*v[1] + v[2]*v[2] + v[3]*v[3];
    return fmaxf(sqrtf(warp_sum(s)), EPSF);
}
__device__ __forceinline__ void project_w(float* v, float k) {
    if (k >= 0.f) return;
    float n = vnorm_w(v);
    float maxn = (1.0f - 1e-5f) * rsqrtf(-k);
    if (n > maxn) {
        float f = maxn / n;
#pragma unroll
        for (int c = 0; c < 4; c++) v[c] *= f;
    }
}
__device__ __forceinline__ void expmap0_w(float* v, float k) {
    float n = vnorm_w(v);
    float s = tan_k(n, k) / n;
#pragma unroll
    for (int c = 0; c < 4; c++) v[c] *= s;
    project_w(v, k);
}
__device__ __forceinline__ void logmap0_w(float* v, float k) {
    float n = vnorm_w(v);
    float s = artan_k(n, k) / n;
#pragma unroll
    for (int c = 0; c < 4; c++) v[c] *= s;
}
__device__ __forceinline__ int lower_bound_batch(const int* __restrict__ b, int val) {
    int lo = 0, hi = NN;
    while (lo < hi) { int mid = (lo + hi) >> 1; if (b[mid] < val) lo = mid + 1; else hi = mid; }
    return lo;
}
__device__ __forceinline__ float bred128(float v, float* sh) {
    v = warp_sum(v);
    int w = threadIdx.x >> 5;
    if ((threadIdx.x & 31) == 0) sh[w] = v;
    __syncthreads();
    float r = sh[0] + sh[1] + sh[2] + sh[3];
    __syncthreads();
    return r;
}

// ---------------- graph prep ----------------
__global__ void k_prep0() {
    int i = blockIdx.x * blockDim.x + threadIdx.x;
    if (i < NN) { g_degcnt[i] = 0; g_cursor[i] = 0; }
}
__global__ void k_deg(const int* __restrict__ col) {
    int e = blockIdx.x * blockDim.x + threadIdx.x;
    if (e < EE) atomicAdd(&g_degcnt[col[e]], 1);
}
__global__ void k_dinvsum() {
    __shared__ int sh[256];
    int t = threadIdx.x;
    int i = blockIdx.x * 256 + t;
    int v = (i < NN) ? g_degcnt[i] : 0;
    if (i < NN) g_dinv[i] = rsqrtf((float)(v + 1));
    sh[t] = v;
    __syncthreads();
#pragma unroll
    for (int o = 128; o; o >>= 1) {
        if (t < o) sh[t] += sh[t + o];
        __syncthreads();
    }
    if (t == 0) g_bsum[blockIdx.x] = sh[0];
}
__global__ void k_scanb() {
    __shared__ int s[256];
    int t = threadIdx.x;
    int v = (t < NB) ? g_bsum[t] : 0;
    s[t] = v;
    __syncthreads();
#pragma unroll
    for (int o = 1; o < 256; o <<= 1) {
        int x = (t >= o) ? s[t - o] : 0;
        __syncthreads();
        s[t] += x;
        __syncthreads();
    }
    if (t < NB) g_boff[t] = s[t] - v;
    if (t == 255) g_off[NN] = s[255];
}
__global__ void k_off() {
    __shared__ int s[256];
    int t = threadIdx.x;
    int i = blockIdx.x * 256 + t;
    int v = (i < NN) ? g_degcnt[i] : 0;
    s[t] = v;
    __syncthreads();
#pragma unroll
    for (int o = 1; o < 256; o <<= 1) {
        int x = (t >= o) ? s[t - o] : 0;
        __syncthreads();
        s[t] += x;
        __syncthreads();
    }
    if (i < NN) g_off[i] = g_boff[blockIdx.x] + s[t] - v;
}
__global__ void k_adj(const int* __restrict__ row, const int* __restrict__ col) {
    int e = blockIdx.x * blockDim.x + threadIdx.x;
    if (e < EE) {
        int d = col[e];
        int p = g_off[d] + atomicAdd(&g_cursor[d], 1);
        g_adj[p] = row[e];
    }
}

// ---------------- layer-0 prep ----------------
__global__ void k_norm0(const float* __restrict__ x) {
    int node = blockIdx.x * 8 + (threadIdx.x >> 5);
    if (node >= NN) return;
    int lane = threadIdx.x & 31;
    float4 xv = ((const float4*)(x + (size_t)node * 128))[lane];
    float s2 = xv.x*xv.x + xv.y*xv.y + xv.z*xv.z + xv.w*xv.w;
    float n = fmaxf(sqrtf(warp_sum(s2)), EPSF);
    if (lane == 0) {
#pragma unroll
        for (int e = 0; e < KEXP; e++) {
            float k = c_curv[e];
            float tk = tan_k(n, k);
            float s = tk / n;
            float vn = fabsf(tk);
            if (k < 0.f) {
                float maxn = (1.0f - 1e-5f) * rsqrtf(-k);
                if (vn > maxn) { s *= maxn / vn; vn = maxn; }
            }
            g_s0[(size_t)e * NN + node] = s;
            g_xn[(size_t)e * NN + node] = fmaxf(vn, EPSF);
        }
    }
}

__global__ void k_bias_all(const float* __restrict__ bsrc, int layer) { // grid=KEXP
    __shared__ float sh[4];
    int e = blockIdx.x;
    float k = c_curv[e];
    int t = threadIdx.x;
    float v = bsrc[e * 128 + t];
    float n2 = bred128(v * v, sh);
    float n = fmaxf(sqrtf(n2), EPSF);
    float p = (tan_k(n, k) / n) * v;
    if (k < 0.f) {
        float p2 = bred128(p * p, sh);
        float pn = fmaxf(sqrtf(p2), EPSF);
        float maxn = (1.0f - 1e-5f) * rsqrtf(-k);
        if (pn > maxn) p *= maxn / pn;
    }
    float p2f = bred128(p * p, sh);
    g_biaspt[(layer * KEXP + e) * 128 + t] = p;
    if (t == 0) g_bp2[layer * KEXP + e] = p2f;
}

// gather-aggregate (CSR) + expmap0 [+ fused logmap0 final layer]: g_t[e] -> g_xm[e]
__global__ void k_agg(int e, float k, int fuseLog) {
    int d = blockIdx.x * 8 + (threadIdx.x >> 5);
    if (d >= NN) return;
    int lane = threadIdx.x & 31;
    const float* __restrict__ t = g_t + (size_t)e * NN * 128;
    float dd = g_dinv[d];
    float4 sv4 = ((const float4*)(t + (size_t)d * 128))[lane];
    float sw = dd * dd;
    float a0 = sw * sv4.x, a1 = sw * sv4.y, a2 = sw * sv4.z, a3 = sw * sv4.w;
    int p0 = g_off[d], p1 = g_off[d + 1];
    for (int p = p0; p < p1; p += 32) {
        int cnt = min(32, p1 - p);
        int sidx = 0; float wv = 0.f;
        if (p + lane < p1) { sidx = g_adj[p + lane]; wv = dd * g_dinv[sidx]; }
        int q = 0;
        for (; q + 4 <= cnt; q += 4) {
            int s0 = __shfl_sync(0xffffffffu, sidx, q);
            int s1 = __shfl_sync(0xffffffffu, sidx, q + 1);
            int s2 = __shfl_sync(0xffffffffu, sidx, q + 2);
            int s3 = __shfl_sync(0xffffffffu, sidx, q + 3);
            float w0 = __shfl_sync(0xffffffffu, wv, q);
            float w1 = __shfl_sync(0xffffffffu, wv, q + 1);
            float w2 = __shfl_sync(0xffffffffu, wv, q + 2);
            float w3 = __shfl_sync(0xffffffffu, wv, q + 3);
            float4 n0 = ((const float4*)(t + (size_t)s0 * 128))[lane];
            float4 n1 = ((const float4*)(t + (size_t)s1 * 128))[lane];
            float4 n2 = ((const float4*)(t + (size_t)s2 * 128))[lane];
            float4 n3 = ((const float4*)(t + (size_t)s3 * 128))[lane];
            a0 = fmaf(w0, n0.x, a0); a1 = fmaf(w0, n0.y, a1);
            a2 = fmaf(w0, n0.z, a2); a3 = fmaf(w0, n0.w, a3);
            a0 = fmaf(w1, n1.x, a0); a1 = fmaf(w1, n1.y, a1);
            a2 = fmaf(w1, n1.z, a2); a3 = fmaf(w1, n1.w, a3);
            a0 = fmaf(w2, n2.x, a0); a1 = fmaf(w2, n2.y, a1);
            a2 = fmaf(w2, n2.z, a2); a3 = fmaf(w2, n2.w, a3);
            a0 = fmaf(w3, n3.x, a0); a1 = fmaf(w3, n3.y, a1);
            a2 = fmaf(w3, n3.z, a2); a3 = fmaf(w3, n3.w, a3);
        }
        for (; q < cnt; q++) {
            int   s = __shfl_sync(0xffffffffu, sidx, q);
            float w = __shfl_sync(0xffffffffu, wv, q);
            float4 nv = ((const float4*)(t + (size_t)s * 128))[lane];
            a0 = fmaf(w, nv.x, a0); a1 = fmaf(w, nv.y, a1);
            a2 = fmaf(w, nv.z, a2); a3 = fmaf(w, nv.w, a3);
        }
    }
    float v[4] = {a0, a1, a2, a3};
    expmap0_w(v, k);
    if (fuseLog) {
        logmap0_w(v, k);
    } else {
        float nv = vnorm_w(v);
        if (lane == 0) g_xn[(size_t)e * NN + d] = nv;
    }
    ((float4*)(g_xm + ((size_t)e * NN + d) * 128))[lane] = make_float4(v[0], v[1], v[2], v[3]);
}

// ---------------- GEMM (+ fused Mobius point epilogue) ----------------
// MODE 0: layer0 — A = x (shared), row scale c=g_s0[e][node], OUT=g_t[e], bias layer 0
// MODE 1: layer1 — A = g_xm[e], c=1, OUT=g_t[e], bias layer 1
// MODE 2: gate   — A = g_g1, plain C to g_gm2
template<int KD, int MODE>
__global__ void gemmf(const float* __restrict__ Xin, const float* __restrict__ W0,
                      int wOfs, int n, int eBase) {
    const float* __restrict__ A;
    float* __restrict__ OUT;
    int lda;
    int eIdx = eBase + blockIdx.y;
    if (MODE == 0) {
        A = Xin; OUT = g_t + (size_t)eIdx * NN * 128; lda = 128;
    } else if (MODE == 1) {
        size_t eo = (size_t)eIdx * NN * 128;
        A = g_xm + eo; OUT = g_t + eo; lda = 128;
    } else {
        A = g_g1; OUT = g_gm2; lda = 32;
    }
    const float* __restrict__ W = W0 + (size_t)eIdx * wOfs;
    __shared__ __align__(16) float As[32][132];
    __shared__ __align__(16) float Bs[32][132];
    __shared__ float red2[128][17];
    __shared__ float redd[128][17];
    __shared__ float reda[128][17];
    __shared__ float2 abArr[128];
    int tid = threadIdx.x;
    int tx = tid & 15, ty = tid >> 4;
    int node0 = blockIdx.x * 128;

    const int bofs = (MODE == 0) ? 0 : KEXP;
    float bpv[8];
    if (MODE < 2) {
        float4 b0 = *(const float4*)(g_biaspt + (bofs + eIdx) * 128 + tx * 4);
        float4 b1 = *(const float4*)(g_biaspt + (bofs + eIdx) * 128 + 64 + tx * 4);
        bpv[0]=b0.x; bpv[1]=b0.y; bpv[2]=b0.z; bpv[3]=b0.w;
        bpv[4]=b1.x; bpv[5]=b1.y; bpv[6]=b1.z; bpv[7]=b1.w;
    }

    float acc[8][8];
#pragma unroll
    for (int m = 0; m < 8; m++)
#pragma unroll
        for (int j = 0; j < 8; j++) acc[m][j] = 0.f;

    for (int k0 = 0; k0 < KD; k0 += 32) {
#pragma unroll
        for (int r = 0; r < 4; r++) {
            int m  = (tid >> 3) + r * 32;
            int kk = (tid & 7) * 4;
            float4 va = make_float4(0.f, 0.f, 0.f, 0.f);
            if (node0 + m < n)
                va = *(const float4*)(A + (size_t)(node0 + m) * lda + k0 + kk);
            As[kk + 0][m] = va.x; As[kk + 1][m] = va.y; As[kk + 2][m] = va.z; As[kk + 3][m] = va.w;
            float4 vb = *(const float4*)(W + (size_t)m * KD + k0 + kk);
            Bs[kk + 0][m] = vb.x; Bs[kk + 1][m] = vb.y; Bs[kk + 2][m] = vb.z; Bs[kk + 3][m] = vb.w;
        }
        __syncthreads();
#pragma unroll
        for (int kk = 0; kk < 32; kk++) {
            float4 a0 = *(const float4*)&As[kk][ty * 4];
            float4 a1 = *(const float4*)&As[kk][64 + ty * 4];
            float4 b0 = *(const float4*)&Bs[kk][tx * 4];
            float4 b1 = *(const float4*)&Bs[kk][64 + tx * 4];
            float a[8] = {a0.x, a0.y, a0.z, a0.w, a1.x, a1.y, a1.z, a1.w};
            float b[8] = {b0.x, b0.y, b0.z, b0.w, b1.x, b1.y, b1.z, b1.w};
#pragma unroll
            for (int m = 0; m < 8; m++)
#pragma unroll
                for (int j = 0; j < 8; j++) acc[m][j] = fmaf(a[m], b[j], acc[m][j]);
        }
        __syncthreads();
    }

    if (MODE == 2) {
#pragma unroll
        for (int m = 0; m < 8; m++) {
            int row = node0 + ((m < 4) ? (ty * 4 + m) : (64 + ty * 4 + m - 4));
            if (row < n) {
                *(float4*)(OUT + (size_t)row * 128 + tx * 4) =
                    make_float4(acc[m][0], acc[m][1], acc[m][2], acc[m][3]);
                *(float4*)(OUT + (size_t)row * 128 + 64 + tx * 4) =
                    make_float4(acc[m][4], acc[m][5], acc[m][6], acc[m][7]);
            }
        }
        return;
    }

    float kv = c_curv[eIdx];
#pragma unroll
    for (int m = 0; m < 8; m++) {
        int rloc = (m < 4) ? (ty * 4 + m) : (64 + ty * 4 + m - 4);
        float s2 = 0.f, sd = 0.f, sa = 0.f;
#pragma unroll
        for (int j = 0; j < 8; j++) {
            float v = acc[m][j];
            s2 = fmaf(v, v, s2); sd = fmaf(v, bpv[j], sd); sa += fabsf(v);
        }
        red2[rloc][tx] = s2; redd[rloc][tx] = sd; reda[rloc][tx] = sa;
    }
    __syncthreads();
    if (tid < 128) {
        int node = node0 + tid;
        if (node < n) {
            float S2 = 0.f, SD = 0.f, SA = 0.f;
#pragma unroll
            for (int i = 0; i < 16; i++) {
                S2 += red2[tid][i]; SD += redd[tid][i]; SA += reda[tid][i];
            }
            float c = 1.f;
            if (MODE == 0) c = g_s0[(size_t)eIdx * NN + node];
            S2 *= c * c; SD *= c; SA *= fabsf(c);
            float alpha, beta;
            if (kv == 0.f) {
                alpha = 1.f; beta = 1.f;
            } else {
                float bp2 = g_bp2[bofs + eIdx];
                float mxn = fmaxf(sqrtf(S2), EPSF);
                float xn  = g_xn[(size_t)eIdx * NN + node];
                float s1 = tan_k(mxn / xn * artan_k(xn, kv), kv) / mxn;
                if (SA == 0.f) s1 = 0.f;
                if (kv < 0.f) {
                    float maxn = (1.0f - 1e-5f) * rsqrtf(-kv);
                    float hn = fmaxf(fabsf(s1) * mxn, EPSF);
                    if (hn > maxn) s1 *= maxn / hn;
                }
                float h2 = s1 * s1 * S2;
                float xy = s1 * SD;
                float num_h = 1.f - 2.f * kv * xy - kv * bp2;
                float num_b = 1.f + kv * h2;
                float den = fmaxf(1.f - 2.f * kv * xy + kv * kv * h2 * bp2, 1e-15f);
                float a1f = num_h * s1 / den;
                float b1f = num_b / den;
                float an2 = fmaxf(a1f * a1f * S2 + 2.f * a1f * b1f * SD + b1f * b1f * bp2, 0.f);
                float an = fmaxf(sqrtf(an2), EPSF);
                float cf2 = 1.f;
                if (kv < 0.f) {
                    float maxn = (1.0f - 1e-5f) * rsqrtf(-kv);
                    if (an > maxn) cf2 = maxn / an;
                }
                float np = fmaxf(an * cf2, EPSF);
                float lg = artan_k(np, kv) / np;
                alpha = lg * cf2 * a1f;
                beta  = lg * cf2 * b1f;
            }
            abArr[tid] = make_float2(alpha * c, beta);
        }
    }
    __syncthreads();
#pragma unroll
    for (int m = 0; m < 8; m++) {
        int rloc = (m < 4) ? (ty * 4 + m) : (64 + ty * 4 + m - 4);
        int row = node0 + rloc;
        if (row < n) {
            float2 ab = abArr[rloc];
            float o[8];
#pragma unroll
            for (int j = 0; j < 8; j++) o[j] = fmaf(ab.x, acc[m][j], ab.y * bpv[j]);
            *(float4*)(OUT + (size_t)row * 128 + tx * 4) =
                make_float4(o[0], o[1], o[2], o[3]);
            *(float4*)(OUT + (size_t)row * 128 + 64 + tx * 4) =
                make_float4(o[4], o[5], o[6], o[7]);
        }
    }
}

// ---------------- gate ----------------
__global__ void k_gate1(const float* __restrict__ x, const float* __restrict__ gw1) {
    __shared__ float wT[128 * 33];
    int tid = threadIdx.x;
    for (int l = tid; l < 4096; l += 256) {
        int j = l >> 7, i = l & 127;
        wT[i * 33 + j] = gw1[l];
    }
    __syncthreads();
    int warp = tid >> 5, lane = tid & 31;
    for (int rep = 0; rep < 4; rep++) {
        int node = blockIdx.x * 32 + rep * 8 + warp;
        if (node < NN) {
            float xv[4];
#pragma unroll
            for (int c = 0; c < 4; c++) xv[c] = x[node * 128 + c * 32 + lane];
            float accv = 0.f;
#pragma unroll
            for (int i = 0; i < 128; i++) {
                float xi = __shfl_sync(0xffffffffu, xv[i >> 5], i & 31);
                accv = fmaf(xi, wT[i * 33 + lane], accv);
            }
            g_gm1[node * 32 + lane] = accv;
        }
    }
}
__global__ void k_gagg1(const float* __restrict__ gb1) {
    int d = blockIdx.x * 8 + (threadIdx.x >> 5);
    if (d >= NN) return;
    int lane = threadIdx.x & 31;
    float dd = g_dinv[d];
    float acc = dd * dd * g_gm1[d * 32 + lane];
    int p0 = g_off[d], p1 = g_off[d + 1];
    for (int p = p0; p < p1; p += 32) {
        int cnt = min(32, p1 - p);
        int sidx = 0; float wv = 0.f;
        if (p + lane < p1) { sidx = g_adj[p + lane]; wv = dd * g_dinv[sidx]; }
        for (int q = 0; q < cnt; q++) {
            int   s = __shfl_sync(0xffffffffu, sidx, q);
            float w = __shfl_sync(0xffffffffu, wv, q);
            acc += w * g_gm1[s * 32 + lane];
        }
    }
    g_g1[d * 32 + lane] = fmaxf(acc + gb1[lane], 0.f);
}
__global__ void k_gagg2(const float* __restrict__ gb2) {
    int d = blockIdx.x * 8 + (threadIdx.x >> 5);
    if (d >= NN) return;
    int lane = threadIdx.x & 31;
    float dd = g_dinv[d];
    float4 sv4 = ((const float4*)(g_gm2 + (size_t)d * 128))[lane];
    float sw = dd * dd;
    float a0 = sw * sv4.x, a1 = sw * sv4.y, a2 = sw * sv4.z, a3 = sw * sv4.w;
    int p0 = g_off[d], p1 = g_off[d + 1];
    for (int p = p0; p < p1; p += 32) {
        int cnt = min(32, p1 - p);
        int sidx = 0; float wv = 0.f;
        if (p + lane < p1) { sidx = g_adj[p + lane]; wv = dd * g_dinv[sidx]; }
        int q = 0;
        for (; q + 4 <= cnt; q += 4) {
            int s0 = __shfl_sync(0xffffffffu, sidx, q);
            int s1 = __shfl_sync(0xffffffffu, sidx, q + 1);
            int s2 = __shfl_sync(0xffffffffu, sidx, q + 2);
            int s3 = __shfl_sync(0xffffffffu, sidx, q + 3);
            float w0 = __shfl_sync(0xffffffffu, wv, q);
            float w1 = __shfl_sync(0xffffffffu, wv, q + 1);
            float w2 = __shfl_sync(0xffffffffu, wv, q + 2);
            float w3 = __shfl_sync(0xffffffffu, wv, q + 3);
            float4 n0 = ((const float4*)(g_gm2 + (size_t)s0 * 128))[lane];
            float4 n1 = ((const float4*)(g_gm2 + (size_t)s1 * 128))[lane];
            float4 n2 = ((const float4*)(g_gm2 + (size_t)s2 * 128))[lane];
            float4 n3 = ((const float4*)(g_gm2 + (size_t)s3 * 128))[lane];
            a0 = fmaf(w0, n0.x, a0); a1 = fmaf(w0, n0.y, a1);
            a2 = fmaf(w0, n0.z, a2); a3 = fmaf(w0, n0.w, a3);
            a0 = fmaf(w1, n1.x, a0); a1 = fmaf(w1, n1.y, a1);
            a2 = fmaf(w1, n1.z, a2); a3 = fmaf(w1, n1.w, a3);
            a0 = fmaf(w2, n2.x, a0); a1 = fmaf(w2, n2.y, a1);
            a2 = fmaf(w2, n2.z, a2); a3 = fmaf(w2, n2.w, a3);
            a0 = fmaf(w3, n3.x, a0); a1 = fmaf(w3, n3.y, a1);
            a2 = fmaf(w3, n3.z, a2); a3 = fmaf(w3, n3.w, a3);
        }
        for (; q < cnt; q++) {
            int   s = __shfl_sync(0xffffffffu, sidx, q);
            float w = __shfl_sync(0xffffffffu, wv, q);
            float4 nv = ((const float4*)(g_gm2 + (size_t)s * 128))[lane];
            a0 = fmaf(w, nv.x, a0); a1 = fmaf(w, nv.y, a1);
            a2 = fmaf(w, nv.z, a2); a3 = fmaf(w, nv.w, a3);
        }
    }
    float4 bv = ((const float4*)gb2)[lane];
    ((float4*)(g_gt + (size_t)d * 128))[lane] = make_float4(
        fmaxf(a0 + bv.x, 0.f), fmaxf(a1 + bv.y, 0.f),
        fmaxf(a2 + bv.z, 0.f), fmaxf(a3 + bv.w, 0.f));
}

// ---------------- pooling (eBase for per-expert launches) ----------------
__global__ void k_pool2(int sel, int eBase, const int* __restrict__ batch) {
    int b = blockIdx.x, e = eBase + blockIdx.y, j = threadIdx.x;
    const float* __restrict__ src = (sel == 0) ? (g_xm + (size_t)e * NN * 128) : g_gt;
    int s = lower_bound_batch(batch, b);
    int ee = lower_bound_batch(batch, b + 1);
    float a0 = 0.f, a1 = 0.f, a2 = 0.f, a3 = 0.f;
    int nd = s;
    for (; nd + 4 <= ee; nd += 4) {
        a0 += src[(size_t)(nd + 0) * 128 + j];
        a1 += src[(size_t)(nd + 1) * 128 + j];
        a2 += src[(size_t)(nd + 2) * 128 + j];
        a3 += src[(size_t)(nd + 3) * 128 + j];
    }
    for (; nd < ee; ++nd) a0 += src[(size_t)nd * 128 + j];
    float sum = (a0 + a1) + (a2 + a3);
    if (sel == 0) g_feat[b * 512 + e * 128 + j] = sum;
    else          g_hgate[b * 128 + j] = sum;
}

// ---------------- finalize ----------------
__global__ void k_finalize(const float* __restrict__ gate_u, const float* __restrict__ tau_raw,
                           float* __restrict__ out, int out_size, const int* __restrict__ batch) {
    __shared__ float sh[4];
    int b = blockIdx.x, j = threadIdx.x;
    int s = lower_bound_batch(batch, b);
    int e = lower_bound_batch(batch, b + 1);
    float c = fmaxf((float)(e - s), 1.0f);
    float hg = g_hgate[b * 128 + j] / c;
    float hn2 = bred128(hg * hg, sh);
    const float curv[4] = {-1.0f, 0.0f, 1.0f, -0.5f};
    float dv[4], tauv[4];
    for (int i = 0; i < 4; i++) {
        float k = curv[i];
        float zn = fmaxf(sqrtf(hn2), EPSF);
        float zk = (tan_k(zn, k) / zn) * hg;
        if (k < 0.f) {
            float z2 = bred128(zk * zk, sh);
            float n = fmaxf(sqrtf(z2), EPSF);
            float maxn = (1.0f - 1e-5f) * rsqrtf(-k);
            if (n > maxn) zk *= maxn / n;
        }
        float u = gate_u[i * 128 + j];
        float un2 = bred128(u * u, sh);
        float un = fmaxf(sqrtf(un2), EPSF);
        float yk = (tan_k(un, k) / un) * u;
        if (k < 0.f) {
            float y2p = bred128(yk * yk, sh);
            float n = fmaxf(sqrtf(y2p), EPSF);
            float maxn = (1.0f - 1e-5f) * rsqrtf(-k);
            if (n > maxn) yk *= maxn / n;
        }
        float xe = -zk;
        float x2 = bred128(xe * xe, sh);
        float y2 = bred128(yk * yk, sh);
        float xy = bred128(xe * yk, sh);
        float nh = 1.f - 2.f * k * xy - k * y2;
        float nb = 1.f + k * x2;
        float den = fmaxf(1.f - 2.f * k * xy + k * k * x2 * y2, 1e-15f);
        float m = (nh * xe + nb * yk) / den;
        if (k < 0.f) {
            float m2p = bred128(m * m, sh);
            float n = fmaxf(sqrtf(m2p), EPSF);
            float maxn = (1.0f - 1e-5f) * rsqrtf(-k);
            if (n > maxn) m *= maxn / n;
        }
        float m2 = bred128(m * m, sh);
        dv[i] = 2.0f * artan_k(fmaxf(sqrtf(m2), EPSF), k);
        float tr = tau_raw[i];
        float sp = (tr > 20.f) ? tr : log1pf(expf(tr));
        tauv[i] = fminf(fmaxf(sp + 0.05f, 0.05f), 10.0f);
    }
    float l[4], mxl = -1e30f;
#pragma unroll
    for (int i = 0; i < 4; i++) { l[i] = -dv[i] / tauv[i]; mxl = fmaxf(mxl, l[i]); }
    float sum = 0.f;
#pragma unroll
    for (int i = 0; i < 4; i++) { l[i] = expf(l[i] - mxl); sum += l[i]; }
    float w[4];
#pragma unroll
    for (int i = 0; i < 4; i++) w[i] = l[i] / sum;
#pragma unroll
    for (int i = 0; i < 4; i++) {
        int idx = b * 512 + i * 128 + j;
        out[idx] = (g_feat[idx] / c) * w[i];
    }
    if (out_size >= 66564) {
        if (j < 4) {
            out[65536 + b * 4 + j] = w[j];
            out[66048 + b * 4 + j] = dv[j];
            if (b == 0) out[66560 + j] = tauv[j];
        }
    }
}

// ---------------- launch (round-11 graph + gate1-first + per-expert pools) --------
extern "C" void kernel_launch(void* const* d_in, const int* in_sizes, int n_in,
                              void* d_out, int out_size) {
    const float* x     = (const float*)d_in[0];
    const int*   ei    = (const int*)d_in[1];
    const int*   row   = ei;
    const int*   col   = ei + EE;
    const int*   batch = (const int*)d_in[2];
    const float* ew1   = (const float*)d_in[3];
    const float* eb1   = (const float*)d_in[4];
    const float* ew2   = (const float*)d_in[5];
    const float* eb2   = (const float*)d_in[6];
    const float* gw1   = (const float*)d_in[7];
    const float* gb1   = (const float*)d_in[8];
    const float* gw2   = (const float*)d_in[9];
    const float* gb2   = (const float*)d_in[10];
    const float* gu    = (const float*)d_in[11];
    const float* traw  = (const float*)d_in[12];
    float* out = (float*)d_out;

    const float curv[4] = {-1.0f, 0.0f, 1.0f, -0.5f};

    const int WG = (NN + 7) / 8;
    const int GG = (NN + 127) / 128;

    static cudaStream_t s2 = nullptr, s3 = nullptr;
    static cudaEvent_t evFork, evPrep, evGate, evPool;
    static cudaEvent_t evA0[KEXP], evG1[KEXP], evA1[KEXP];
    if (!s2) {
        cudaStreamCreateWithFlags(&s2, cudaStreamNonBlocking);
        cudaStreamCreateWithFlags(&s3, cudaStreamNonBlocking);
        cudaEventCreateWithFlags(&evFork, cudaEventDisableTiming);
        cudaEventCreateWithFlags(&evPrep, cudaEventDisableTiming);
        cudaEventCreateWithFlags(&evGate, cudaEventDisableTiming);
        cudaEventCreateWithFlags(&evPool, cudaEventDisableTiming);
        for (int e = 0; e < KEXP; e++) {
            cudaEventCreateWithFlags(&evA0[e], cudaEventDisableTiming);
            cudaEventCreateWithFlags(&evG1[e], cudaEventDisableTiming);
            cudaEventCreateWithFlags(&evA1[e], cudaEventDisableTiming);
        }
    }

    // fork side streams from the capture-origin (default) stream
    cudaEventRecord(evFork, 0);
    cudaStreamWaitEvent(s2, evFork, 0);
    cudaStreamWaitEvent(s3, evFork, 0);

    // main: expert path head (kernel slots 1,2,4 — slot 3 is s2's gate1)
    k_bias_all<<<KEXP, 128>>>(eb1, 0);                               // 1
    k_norm0<<<WG, 256>>>(x);                                         // 2
    k_gate1<<<(NN + 31) / 32, 256, 0, s2>>>(x, gw1);                 // 3 (s2, no prep dep)
    gemmf<128, 0><<<dim3(GG, KEXP), 256>>>(x, ew1, 16384, NN, 0);    // 4: layer0 GEMM+point

    // s3: layer-1 bias prep (independent; separate bias slot)
    k_bias_all<<<KEXP, 128, 0, s3>>>(eb2, 1);

    // s2: graph prep chain (after gate1), then gate aggregation path
    k_prep0<<<(NN + 255) / 256, 256, 0, s2>>>();
    k_deg<<<(EE + 255) / 256, 256, 0, s2>>>(col);
    k_dinvsum<<<NB, 256, 0, s2>>>();
    k_scanb<<<1, 256, 0, s2>>>();
    k_off<<<NB, 256, 0, s2>>>();
    k_adj<<<(EE + 255) / 256, 256, 0, s2>>>(row, col);
    cudaEventRecord(evPrep, s2);
    k_gagg1<<<WG, 256, 0, s2>>>(gb1);
    gemmf<32, 2><<<dim3(GG, 1), 256, 0, s2>>>(nullptr, gw2, 0, NN, 0);
    k_gagg2<<<WG, 256, 0, s2>>>(gb2);
    k_pool2<<<dim3(BB, 1), 128, 0, s2>>>(1, 0, batch);
    cudaEventRecord(evGate, s2);

    // main: layer-0 aggs, each feeding a per-expert layer-1 GEMM on s3
    cudaStreamWaitEvent(0, evPrep, 0);
    for (int e = 0; e < KEXP; e++) {
        k_agg<<<WG, 256>>>(e, curv[e], 0);
        cudaEventRecord(evA0[e], 0);
        cudaStreamWaitEvent(s3, evA0[e], 0);
        gemmf<128, 1><<<dim3(GG, 1), 256, 0, s3>>>(nullptr, ew2, 16384, NN, e);
        cudaEventRecord(evG1[e], s3);
    }
    // main: layer-1 aggs; per-expert pooling moves off-chain to s3
    for (int e = 0; e < KEXP; e++) {
        cudaStreamWaitEvent(0, evG1[e], 0);
        k_agg<<<WG, 256>>>(e, curv[e], 1);
        cudaEventRecord(evA1[e], 0);
        cudaStreamWaitEvent(s3, evA1[e], 0);
        k_pool2<<<dim3(BB, 1), 128, 0, s3>>>(0, e, batch);
    }
    cudaEventRecord(evPool, s3);

    // join gate path + pools, finalize
    cudaStreamWaitEvent(0, evPool, 0);
    cudaStreamWaitEvent(0, evGate, 0);
    k_finalize<<<BB, 128>>>(gu, traw, out, out_size, batch);
}

// round 16
// speedup vs baseline: 1.5060x; 1.1727x over previous
#include <cuda_runtime.h>
#include <math.h>
#include <stdint.h>

#define NN   50000
#define EE   800000
#define BB   128
#define KEXP 4
#define EPSF 1e-15f
#define NB   ((NN + 255) / 256)   // 196

__constant__ float c_curv[KEXP] = {-1.0f, 0.0f, 1.0f, -0.5f};

// ---------------- scratch (device globals; no runtime allocs) ----------------
__device__ float g_dinv[NN];
__device__ int   g_degcnt[NN];
__device__ int   g_off[NN + 1];
__device__ int   g_cursor[NN];
__device__ int   g_adj[EE];
__device__ int   g_bsum[NB];
__device__ int   g_boff[NB];
__device__ float g_xm[(size_t)KEXP * NN * 128];
__device__ float g_t [(size_t)KEXP * NN * 128];
__device__ float g_xn[(size_t)KEXP * NN];
__device__ float g_s0[(size_t)KEXP * NN];
__device__ float g_gm1[NN * 32];
__device__ float g_g1 [NN * 32];
__device__ float g_gm2[NN * 128];
__device__ float g_gt [NN * 128];
__device__ float g_feat[BB * 512];
__device__ float g_hgate[BB * 128];
__device__ float g_biaspt[2 * KEXP * 128];   // [layer][expert][128]
__device__ float g_bp2[2 * KEXP];

// ---------------- math helpers (all fp32) ----------------
__device__ __forceinline__ float tan_k(float x, float k) {
    if (k > 0.f) { float sk = sqrtf(k);  return tanf(x * sk) / sk; }
    if (k < 0.f) { float sk = sqrtf(-k); return tanhf(x * sk) / sk; }
    return x;
}
__device__ __forceinline__ float artan_k(float x, float k) {
    if (k > 0.f) { float sk = sqrtf(k);  return atanf(x * sk) / sk; }
    if (k < 0.f) {
        float sk = sqrtf(-k);
        float z = fminf(fmaxf(x * sk, -1.0f + 1e-7f), 1.0f - 1e-7f);
        return atanhf(z) / sk;
    }
    return x;
}
__device__ __forceinline__ float warp_sum(float v) {
#pragma unroll
    for (int o = 16; o; o >>= 1) v += __shfl_xor_sync(0xffffffffu, v, o);
    return v;
}
__device__ __forceinline__ float vnorm_w(const float* v) {
    float s = v[0]*v[0] + v[1]*v[1] + v[2]*v[2] + v[3]*v[3];
    return fmaxf(sqrtf(warp_sum(s)), EPSF);
}
__device__ __forceinline__ void project_w(float* v, float k) {
    if (k >= 0.f) return;
    float n = vnorm_w(v);
    float maxn = (1.0f - 1e-5f) * rsqrtf(-k);
    if (n > maxn) {
        float f = maxn / n;
#pragma unroll
        for (int c = 0; c < 4; c++) v[c] *= f;
    }
}
__device__ __forceinline__ void expmap0_w(float* v, float k) {
    float n = vnorm_w(v);
    float s = tan_k(n, k) / n;
#pragma unroll
    for (int c = 0; c < 4; c++) v[c] *= s;
    project_w(v, k);
}
__device__ __forceinline__ void logmap0_w(float* v, float k) {
    float n = vnorm_w(v);
    float s = artan_k(n, k) / n;
#pragma unroll
    for (int c = 0; c < 4; c++) v[c] *= s;
}
__device__ __forceinline__ int lower_bound_batch(const int* __restrict__ b, int val) {
    int lo = 0, hi = NN;
    while (lo < hi) { int mid = (lo + hi) >> 1; if (b[mid] < val) lo = mid + 1; else hi = mid; }
    return lo;
}
__device__ __forceinline__ float bred128(float v, float* sh) {
    v = warp_sum(v);
    int w = threadIdx.x >> 5;
    if ((threadIdx.x & 31) == 0) sh[w] = v;
    __syncthreads();
    float r = sh[0] + sh[1] + sh[2] + sh[3];
    __syncthreads();
    return r;
}

// ---------------- graph prep ----------------
__global__ void k_prep0() {
    int i = blockIdx.x * blockDim.x + threadIdx.x;
    if (i < NN) { g_degcnt[i] = 0; g_cursor[i] = 0; }
}
__global__ void k_deg(const int* __restrict__ col) {
    int e = blockIdx.x * blockDim.x + threadIdx.x;
    if (e < EE) atomicAdd(&g_degcnt[col[e]], 1);
}
__global__ void k_dinvsum() {
    __shared__ int sh[256];
    int t = threadIdx.x;
    int i = blockIdx.x * 256 + t;
    int v = (i < NN) ? g_degcnt[i] : 0;
    if (i < NN) g_dinv[i] = rsqrtf((float)(v + 1));
    sh[t] = v;
    __syncthreads();
#pragma unroll
    for (int o = 128; o; o >>= 1) {
        if (t < o) sh[t] += sh[t + o];
        __syncthreads();
    }
    if (t == 0) g_bsum[blockIdx.x] = sh[0];
}
__global__ void k_scanb() {
    __shared__ int s[256];
    int t = threadIdx.x;
    int v = (t < NB) ? g_bsum[t] : 0;
    s[t] = v;
    __syncthreads();
#pragma unroll
    for (int o = 1; o < 256; o <<= 1) {
        int x = (t >= o) ? s[t - o] : 0;
        __syncthreads();
        s[t] += x;
        __syncthreads();
    }
    if (t < NB) g_boff[t] = s[t] - v;
    if (t == 255) g_off[NN] = s[255];
}
__global__ void k_off() {
    __shared__ int s[256];
    int t = threadIdx.x;
    int i = blockIdx.x * 256 + t;
    int v = (i < NN) ? g_degcnt[i] : 0;
    s[t] = v;
    __syncthreads();
#pragma unroll
    for (int o = 1; o < 256; o <<= 1) {
        int x = (t >= o) ? s[t - o] : 0;
        __syncthreads();
        s[t] += x;
        __syncthreads();
    }
    if (i < NN) g_off[i] = g_boff[blockIdx.x] + s[t] - v;
}
__global__ void k_adj(const int* __restrict__ row, const int* __restrict__ col) {
    int e = blockIdx.x * blockDim.x + threadIdx.x;
    if (e < EE) {
        int d = col[e];
        int p = g_off[d] + atomicAdd(&g_cursor[d], 1);
        g_adj[p] = row[e];
    }
}

// ---------------- layer-0 prep: per-node expmap0 scale + norm for all experts --------
__global__ void k_norm0(const float* __restrict__ x) {
    int node = blockIdx.x * 8 + (threadIdx.x >> 5);
    if (node >= NN) return;
    int lane = threadIdx.x & 31;
    float4 xv = ((const float4*)(x + (size_t)node * 128))[lane];
    float s2 = xv.x*xv.x + xv.y*xv.y + xv.z*xv.z + xv.w*xv.w;
    float n = fmaxf(sqrtf(warp_sum(s2)), EPSF);
    if (lane == 0) {
#pragma unroll
        for (int e = 0; e < KEXP; e++) {
            float k = c_curv[e];
            float tk = tan_k(n, k);
            float s = tk / n;
            float vn = fabsf(tk);
            if (k < 0.f) {
                float maxn = (1.0f - 1e-5f) * rsqrtf(-k);
                if (vn > maxn) { s *= maxn / vn; vn = maxn; }
            }
            g_s0[(size_t)e * NN + node] = s;
            g_xn[(size_t)e * NN + node] = fmaxf(vn, EPSF);
        }
    }
}

__global__ void k_bias_all(const float* __restrict__ bsrc, int layer) { // grid=KEXP
    __shared__ float sh[4];
    int e = blockIdx.x;
    float k = c_curv[e];
    int t = threadIdx.x;
    float v = bsrc[e * 128 + t];
    float n2 = bred128(v * v, sh);
    float n = fmaxf(sqrtf(n2), EPSF);
    float p = (tan_k(n, k) / n) * v;
    if (k < 0.f) {
        float p2 = bred128(p * p, sh);
        float pn = fmaxf(sqrtf(p2), EPSF);
        float maxn = (1.0f - 1e-5f) * rsqrtf(-k);
        if (pn > maxn) p *= maxn / pn;
    }
    float p2f = bred128(p * p, sh);
    g_biaspt[(layer * KEXP + e) * 128 + t] = p;
    if (t == 0) g_bp2[layer * KEXP + e] = p2f;
}

// gather-aggregate (CSR) + expmap0 [+ fused logmap0 final layer]: g_t[e] -> g_xm[e]
__global__ void k_agg(int e, float k, int fuseLog) {
    int d = blockIdx.x * 8 + (threadIdx.x >> 5);
    if (d >= NN) return;
    int lane = threadIdx.x & 31;
    const float* __restrict__ t = g_t + (size_t)e * NN * 128;
    float dd = g_dinv[d];
    float4 sv4 = ((const float4*)(t + (size_t)d * 128))[lane];
    float sw = dd * dd;
    float a0 = sw * sv4.x, a1 = sw * sv4.y, a2 = sw * sv4.z, a3 = sw * sv4.w;
    int p0 = g_off[d], p1 = g_off[d + 1];
    for (int p = p0; p < p1; p += 32) {
        int cnt = min(32, p1 - p);
        int sidx = 0; float wv = 0.f;
        if (p + lane < p1) { sidx = g_adj[p + lane]; wv = dd * g_dinv[sidx]; }
        int q = 0;
        for (; q + 4 <= cnt; q += 4) {
            int s0 = __shfl_sync(0xffffffffu, sidx, q);
            int s1 = __shfl_sync(0xffffffffu, sidx, q + 1);
            int s2 = __shfl_sync(0xffffffffu, sidx, q + 2);
            int s3 = __shfl_sync(0xffffffffu, sidx, q + 3);
            float w0 = __shfl_sync(0xffffffffu, wv, q);
            float w1 = __shfl_sync(0xffffffffu, wv, q + 1);
            float w2 = __shfl_sync(0xffffffffu, wv, q + 2);
            float w3 = __shfl_sync(0xffffffffu, wv, q + 3);
            float4 n0 = ((const float4*)(t + (size_t)s0 * 128))[lane];
            float4 n1 = ((const float4*)(t + (size_t)s1 * 128))[lane];
            float4 n2 = ((const float4*)(t + (size_t)s2 * 128))[lane];
            float4 n3 = ((const float4*)(t + (size_t)s3 * 128))[lane];
            a0 = fmaf(w0, n0.x, a0); a1 = fmaf(w0, n0.y, a1);
            a2 = fmaf(w0, n0.z, a2); a3 = fmaf(w0, n0.w, a3);
            a0 = fmaf(w1, n1.x, a0); a1 = fmaf(w1, n1.y, a1);
            a2 = fmaf(w1, n1.z, a2); a3 = fmaf(w1, n1.w, a3);
            a0 = fmaf(w2, n2.x, a0); a1 = fmaf(w2, n2.y, a1);
            a2 = fmaf(w2, n2.z, a2); a3 = fmaf(w2, n2.w, a3);
            a0 = fmaf(w3, n3.x, a0); a1 = fmaf(w3, n3.y, a1);
            a2 = fmaf(w3, n3.z, a2); a3 = fmaf(w3, n3.w, a3);
        }
        for (; q < cnt; q++) {
            int   s = __shfl_sync(0xffffffffu, sidx, q);
            float w = __shfl_sync(0xffffffffu, wv, q);
            float4 nv = ((const float4*)(t + (size_t)s * 128))[lane];
            a0 = fmaf(w, nv.x, a0); a1 = fmaf(w, nv.y, a1);
            a2 = fmaf(w, nv.z, a2); a3 = fmaf(w, nv.w, a3);
        }
    }
    float v[4] = {a0, a1, a2, a3};
    expmap0_w(v, k);
    if (fuseLog) {
        logmap0_w(v, k);
    } else {
        float nv = vnorm_w(v);
        if (lane == 0) g_xn[(size_t)e * NN + d] = nv;
    }
    ((float4*)(g_xm + ((size_t)e * NN + d) * 128))[lane] = make_float4(v[0], v[1], v[2], v[3]);
}

// ---------------- GEMM (+ fused Mobius point epilogue) ----------------
// MODE 0: layer0 — A = x (shared), row scale c=g_s0[e][node], OUT=g_t[e], bias layer 0
// MODE 1: layer1 — A = g_xm[e], c=1, OUT=g_t[e], bias layer 1
// MODE 2: gate   — A = g_g1, plain C to g_gm2
// eIdx = eBase + blockIdx.y (eBase enables per-expert launches on side streams)
template<int KD, int MODE>
__global__ void gemmf(const float* __restrict__ Xin, const float* __restrict__ W0,
                      int wOfs, int n, int eBase) {
    const float* __restrict__ A;
    float* __restrict__ OUT;
    int lda;
    int eIdx = eBase + blockIdx.y;
    if (MODE == 0) {
        A = Xin; OUT = g_t + (size_t)eIdx * NN * 128; lda = 128;
    } else if (MODE == 1) {
        size_t eo = (size_t)eIdx * NN * 128;
        A = g_xm + eo; OUT = g_t + eo; lda = 128;
    } else {
        A = g_g1; OUT = g_gm2; lda = 32;
    }
    const float* __restrict__ W = W0 + (size_t)eIdx * wOfs;
    __shared__ __align__(16) float As[32][132];
    __shared__ __align__(16) float Bs[32][132];
    __shared__ float red2[128][17];
    __shared__ float redd[128][17];
    __shared__ float reda[128][17];
    __shared__ float2 abArr[128];
    int tid = threadIdx.x;
    int tx = tid & 15, ty = tid >> 4;
    int node0 = blockIdx.x * 128;

    const int bofs = (MODE == 0) ? 0 : KEXP;   // bias layer offset
    float bpv[8];
    if (MODE < 2) {
        float4 b0 = *(const float4*)(g_biaspt + (bofs + eIdx) * 128 + tx * 4);
        float4 b1 = *(const float4*)(g_biaspt + (bofs + eIdx) * 128 + 64 + tx * 4);
        bpv[0]=b0.x; bpv[1]=b0.y; bpv[2]=b0.z; bpv[3]=b0.w;
        bpv[4]=b1.x; bpv[5]=b1.y; bpv[6]=b1.z; bpv[7]=b1.w;
    }

    float acc[8][8];
#pragma unroll
    for (int m = 0; m < 8; m++)
#pragma unroll
        for (int j = 0; j < 8; j++) acc[m][j] = 0.f;

    for (int k0 = 0; k0 < KD; k0 += 32) {
#pragma unroll
        for (int r = 0; r < 4; r++) {
            int m  = (tid >> 3) + r * 32;
            int kk = (tid & 7) * 4;
            float4 va = make_float4(0.f, 0.f, 0.f, 0.f);
            if (node0 + m < n)
                va = *(const float4*)(A + (size_t)(node0 + m) * lda + k0 + kk);
            As[kk + 0][m] = va.x; As[kk + 1][m] = va.y; As[kk + 2][m] = va.z; As[kk + 3][m] = va.w;
            float4 vb = *(const float4*)(W + (size_t)m * KD + k0 + kk);
            Bs[kk + 0][m] = vb.x; Bs[kk + 1][m] = vb.y; Bs[kk + 2][m] = vb.z; Bs[kk + 3][m] = vb.w;
        }
        __syncthreads();
#pragma unroll
        for (int kk = 0; kk < 32; kk++) {
            float4 a0 = *(const float4*)&As[kk][ty * 4];
            float4 a1 = *(const float4*)&As[kk][64 + ty * 4];
            float4 b0 = *(const float4*)&Bs[kk][tx * 4];
            float4 b1 = *(const float4*)&Bs[kk][64 + tx * 4];
            float a[8] = {a0.x, a0.y, a0.z, a0.w, a1.x, a1.y, a1.z, a1.w};
            float b[8] = {b0.x, b0.y, b0.z, b0.w, b1.x, b1.y, b1.z, b1.w};
#pragma unroll
            for (int m = 0; m < 8; m++)
#pragma unroll
                for (int j = 0; j < 8; j++) acc[m][j] = fmaf(a[m], b[j], acc[m][j]);
        }
        __syncthreads();
    }

    if (MODE == 2) {
#pragma unroll
        for (int m = 0; m < 8; m++) {
            int row = node0 + ((m < 4) ? (ty * 4 + m) : (64 + ty * 4 + m - 4));
            if (row < n) {
                *(float4*)(OUT + (size_t)row * 128 + tx * 4) =
                    make_float4(acc[m][0], acc[m][1], acc[m][2], acc[m][3]);
                *(float4*)(OUT + (size_t)row * 128 + 64 + tx * 4) =
                    make_float4(acc[m][4], acc[m][5], acc[m][6], acc[m][7]);
            }
        }
        return;
    }

    float kv = c_curv[eIdx];
#pragma unroll
    for (int m = 0; m < 8; m++) {
        int rloc = (m < 4) ? (ty * 4 + m) : (64 + ty * 4 + m - 4);
        float s2 = 0.f, sd = 0.f, sa = 0.f;
#pragma unroll
        for (int j = 0; j < 8; j++) {
            float v = acc[m][j];
            s2 = fmaf(v, v, s2); sd = fmaf(v, bpv[j], sd); sa += fabsf(v);
        }
        red2[rloc][tx] = s2; redd[rloc][tx] = sd; reda[rloc][tx] = sa;
    }
    __syncthreads();
    if (tid < 128) {
        int node = node0 + tid;
        if (node < n) {
            float S2 = 0.f, SD = 0.f, SA = 0.f;
#pragma unroll
            for (int i = 0; i < 16; i++) {
                S2 += red2[tid][i]; SD += redd[tid][i]; SA += reda[tid][i];
            }
            float c = 1.f;
            if (MODE == 0) c = g_s0[(size_t)eIdx * NN + node];
            S2 *= c * c; SD *= c; SA *= fabsf(c);
            float alpha, beta;
            if (kv == 0.f) {
                alpha = 1.f; beta = 1.f;
            } else {
                float bp2 = g_bp2[bofs + eIdx];
                float mxn = fmaxf(sqrtf(S2), EPSF);
                float xn  = g_xn[(size_t)eIdx * NN + node];
                float s1 = tan_k(mxn / xn * artan_k(xn, kv), kv) / mxn;
                if (SA == 0.f) s1 = 0.f;
                if (kv < 0.f) {
                    float maxn = (1.0f - 1e-5f) * rsqrtf(-kv);
                    float hn = fmaxf(fabsf(s1) * mxn, EPSF);
                    if (hn > maxn) s1 *= maxn / hn;
                }
                float h2 = s1 * s1 * S2;
                float xy = s1 * SD;
                float num_h = 1.f - 2.f * kv * xy - kv * bp2;
                float num_b = 1.f + kv * h2;
                float den = fmaxf(1.f - 2.f * kv * xy + kv * kv * h2 * bp2, 1e-15f);
                float a1f = num_h * s1 / den;
                float b1f = num_b / den;
                float an2 = fmaxf(a1f * a1f * S2 + 2.f * a1f * b1f * SD + b1f * b1f * bp2, 0.f);
                float an = fmaxf(sqrtf(an2), EPSF);
                float cf2 = 1.f;
                if (kv < 0.f) {
                    float maxn = (1.0f - 1e-5f) * rsqrtf(-kv);
                    if (an > maxn) cf2 = maxn / an;
                }
                float np = fmaxf(an * cf2, EPSF);
                float lg = artan_k(np, kv) / np;
                alpha = lg * cf2 * a1f;
                beta  = lg * cf2 * b1f;
            }
            abArr[tid] = make_float2(alpha * c, beta);
        }
    }
    __syncthreads();
#pragma unroll
    for (int m = 0; m < 8; m++) {
        int rloc = (m < 4) ? (ty * 4 + m) : (64 + ty * 4 + m - 4);
        int row = node0 + rloc;
        if (row < n) {
            float2 ab = abArr[rloc];
            float o[8];
#pragma unroll
            for (int j = 0; j < 8; j++) o[j] = fmaf(ab.x, acc[m][j], ab.y * bpv[j]);
            *(float4*)(OUT + (size_t)row * 128 + tx * 4) =
                make_float4(o[0], o[1], o[2], o[3]);
            *(float4*)(OUT + (size_t)row * 128 + 64 + tx * 4) =
                make_float4(o[4], o[5], o[6], o[7]);
        }
    }
}

// ---------------- gate ----------------
__global__ void k_gate1(const float* __restrict__ x, const float* __restrict__ gw1) {
    __shared__ float wT[128 * 33];
    int tid = threadIdx.x;
    for (int l = tid; l < 4096; l += 256) {
        int j = l >> 7, i = l & 127;
        wT[i * 33 + j] = gw1[l];
    }
    __syncthreads();
    int warp = tid >> 5, lane = tid & 31;
    for (int rep = 0; rep < 4; rep++) {
        int node = blockIdx.x * 32 + rep * 8 + warp;
        if (node < NN) {
            float xv[4];
#pragma unroll
            for (int c = 0; c < 4; c++) xv[c] = x[node * 128 + c * 32 + lane];
            float accv = 0.f;
#pragma unroll
            for (int i = 0; i < 128; i++) {
                float xi = __shfl_sync(0xffffffffu, xv[i >> 5], i & 31);
                accv = fmaf(xi, wT[i * 33 + lane], accv);
            }
            g_gm1[node * 32 + lane] = accv;
        }
    }
}
__global__ void k_gagg1(const float* __restrict__ gb1) {
    int d = blockIdx.x * 8 + (threadIdx.x >> 5);
    if (d >= NN) return;
    int lane = threadIdx.x & 31;
    float dd = g_dinv[d];
    float acc = dd * dd * g_gm1[d * 32 + lane];
    int p0 = g_off[d], p1 = g_off[d + 1];
    for (int p = p0; p < p1; p += 32) {
        int cnt = min(32, p1 - p);
        int sidx = 0; float wv = 0.f;
        if (p + lane < p1) { sidx = g_adj[p + lane]; wv = dd * g_dinv[sidx]; }
        for (int q = 0; q < cnt; q++) {
            int   s = __shfl_sync(0xffffffffu, sidx, q);
            float w = __shfl_sync(0xffffffffu, wv, q);
            acc += w * g_gm1[s * 32 + lane];
        }
    }
    g_g1[d * 32 + lane] = fmaxf(acc + gb1[lane], 0.f);
}
__global__ void k_gagg2(const float* __restrict__ gb2) {
    int d = blockIdx.x * 8 + (threadIdx.x >> 5);
    if (d >= NN) return;
    int lane = threadIdx.x & 31;
    float dd = g_dinv[d];
    float4 sv4 = ((const float4*)(g_gm2 + (size_t)d * 128))[lane];
    float sw = dd * dd;
    float a0 = sw * sv4.x, a1 = sw * sv4.y, a2 = sw * sv4.z, a3 = sw * sv4.w;
    int p0 = g_off[d], p1 = g_off[d + 1];
    for (int p = p0; p < p1; p += 32) {
        int cnt = min(32, p1 - p);
        int sidx = 0; float wv = 0.f;
        if (p + lane < p1) { sidx = g_adj[p + lane]; wv = dd * g_dinv[sidx]; }
        int q = 0;
        for (; q + 4 <= cnt; q += 4) {
            int s0 = __shfl_sync(0xffffffffu, sidx, q);
            int s1 = __shfl_sync(0xffffffffu, sidx, q + 1);
            int s2 = __shfl_sync(0xffffffffu, sidx, q + 2);
            int s3 = __shfl_sync(0xffffffffu, sidx, q + 3);
            float w0 = __shfl_sync(0xffffffffu, wv, q);
            float w1 = __shfl_sync(0xffffffffu, wv, q + 1);
            float w2 = __shfl_sync(0xffffffffu, wv, q + 2);
            float w3 = __shfl_sync(0xffffffffu, wv, q + 3);
            float4 n0 = ((const float4*)(g_gm2 + (size_t)s0 * 128))[lane];
            float4 n1 = ((const float4*)(g_gm2 + (size_t)s1 * 128))[lane];
            float4 n2 = ((const float4*)(g_gm2 + (size_t)s2 * 128))[lane];
            float4 n3 = ((const float4*)(g_gm2 + (size_t)s3 * 128))[lane];
            a0 = fmaf(w0, n0.x, a0); a1 = fmaf(w0, n0.y, a1);
            a2 = fmaf(w0, n0.z, a2); a3 = fmaf(w0, n0.w, a3);
            a0 = fmaf(w1, n1.x, a0); a1 = fmaf(w1, n1.y, a1);
            a2 = fmaf(w1, n1.z, a2); a3 = fmaf(w1, n1.w, a3);
            a0 = fmaf(w2, n2.x, a0); a1 = fmaf(w2, n2.y, a1);
            a2 = fmaf(w2, n2.z, a2); a3 = fmaf(w2, n2.w, a3);
            a0 = fmaf(w3, n3.x, a0); a1 = fmaf(w3, n3.y, a1);
            a2 = fmaf(w3, n3.z, a2); a3 = fmaf(w3, n3.w, a3);
        }
        for (; q < cnt; q++) {
            int   s = __shfl_sync(0xffffffffu, sidx, q);
            float w = __shfl_sync(0xffffffffu, wv, q);
            float4 nv = ((const float4*)(g_gm2 + (size_t)s * 128))[lane];
            a0 = fmaf(w, nv.x, a0); a1 = fmaf(w, nv.y, a1);
            a2 = fmaf(w, nv.z, a2); a3 = fmaf(w, nv.w, a3);
        }
    }
    float4 bv = ((const float4*)gb2)[lane];
    ((float4*)(g_gt + (size_t)d * 128))[lane] = make_float4(
        fmaxf(a0 + bv.x, 0.f), fmaxf(a1 + bv.y, 0.f),
        fmaxf(a2 + bv.z, 0.f), fmaxf(a3 + bv.w, 0.f));
}

// ---------------- pooling ----------------
__global__ void k_pool2(int sel, const int* __restrict__ batch) {
    int b = blockIdx.x, e = blockIdx.y, j = threadIdx.x;
    const float* __restrict__ src = (sel == 0) ? (g_xm + (size_t)e * NN * 128) : g_gt;
    int s = lower_bound_batch(batch, b);
    int ee = lower_bound_batch(batch, b + 1);
    float a0 = 0.f, a1 = 0.f, a2 = 0.f, a3 = 0.f;
    int nd = s;
    for (; nd + 4 <= ee; nd += 4) {
        a0 += src[(size_t)(nd + 0) * 128 + j];
        a1 += src[(size_t)(nd + 1) * 128 + j];
        a2 += src[(size_t)(nd + 2) * 128 + j];
        a3 += src[(size_t)(nd + 3) * 128 + j];
    }
    for (; nd < ee; ++nd) a0 += src[(size_t)nd * 128 + j];
    float sum = (a0 + a1) + (a2 + a3);
    if (sel == 0) g_feat[b * 512 + e * 128 + j] = sum;
    else          g_hgate[b * 128 + j] = sum;
}

// ---------------- finalize ----------------
__global__ void k_finalize(const float* __restrict__ gate_u, const float* __restrict__ tau_raw,
                           float* __restrict__ out, int out_size, const int* __restrict__ batch) {
    __shared__ float sh[4];
    int b = blockIdx.x, j = threadIdx.x;
    int s = lower_bound_batch(batch, b);
    int e = lower_bound_batch(batch, b + 1);
    float c = fmaxf((float)(e - s), 1.0f);
    float hg = g_hgate[b * 128 + j] / c;
    float hn2 = bred128(hg * hg, sh);
    const float curv[4] = {-1.0f, 0.0f, 1.0f, -0.5f};
    float dv[4], tauv[4];
    for (int i = 0; i < 4; i++) {
        float k = curv[i];
        float zn = fmaxf(sqrtf(hn2), EPSF);
        float zk = (tan_k(zn, k) / zn) * hg;
        if (k < 0.f) {
            float z2 = bred128(zk * zk, sh);
            float n = fmaxf(sqrtf(z2), EPSF);
            float maxn = (1.0f - 1e-5f) * rsqrtf(-k);
            if (n > maxn) zk *= maxn / n;
        }
        float u = gate_u[i * 128 + j];
        float un2 = bred128(u * u, sh);
        float un = fmaxf(sqrtf(un2), EPSF);
        float yk = (tan_k(un, k) / un) * u;
        if (k < 0.f) {
            float y2p = bred128(yk * yk, sh);
            float n = fmaxf(sqrtf(y2p), EPSF);
            float maxn = (1.0f - 1e-5f) * rsqrtf(-k);
            if (n > maxn) yk *= maxn / n;
        }
        float xe = -zk;
        float x2 = bred128(xe * xe, sh);
        float y2 = bred128(yk * yk, sh);
        float xy = bred128(xe * yk, sh);
        float nh = 1.f - 2.f * k * xy - k * y2;
        float nb = 1.f + k * x2;
        float den = fmaxf(1.f - 2.f * k * xy + k * k * x2 * y2, 1e-15f);
        float m = (nh * xe + nb * yk) / den;
        if (k < 0.f) {
            float m2p = bred128(m * m, sh);
            float n = fmaxf(sqrtf(m2p), EPSF);
            float maxn = (1.0f - 1e-5f) * rsqrtf(-k);
            if (n > maxn) m *= maxn / n;
        }
        float m2 = bred128(m * m, sh);
        dv[i] = 2.0f * artan_k(fmaxf(sqrtf(m2), EPSF), k);
        float tr = tau_raw[i];
        float sp = (tr > 20.f) ? tr : log1pf(expf(tr));
        tauv[i] = fminf(fmaxf(sp + 0.05f, 0.05f), 10.0f);
    }
    float l[4], mxl = -1e30f;
#pragma unroll
    for (int i = 0; i < 4; i++) { l[i] = -dv[i] / tauv[i]; mxl = fmaxf(mxl, l[i]); }
    float sum = 0.f;
#pragma unroll
    for (int i = 0; i < 4; i++) { l[i] = expf(l[i] - mxl); sum += l[i]; }
    float w[4];
#pragma unroll
    for (int i = 0; i < 4; i++) w[i] = l[i] / sum;
#pragma unroll
    for (int i = 0; i < 4; i++) {
        int idx = b * 512 + i * 128 + j;
        out[idx] = (g_feat[idx] / c) * w[i];
    }
    if (out_size >= 66564) {
        if (j < 4) {
            out[65536 + b * 4 + j] = w[j];
            out[66048 + b * 4 + j] = dv[j];
            if (b == 0) out[66560 + j] = tauv[j];
        }
    }
}

// ---------------- launch (3 streams: expert aggs | prep+gate | layer-1 gemms) --------
extern "C" void kernel_launch(void* const* d_in, const int* in_sizes, int n_in,
                              void* d_out, int out_size) {
    const float* x     = (const float*)d_in[0];
    const int*   ei    = (const int*)d_in[1];
    const int*   row   = ei;
    const int*   col   = ei + EE;
    const int*   batch = (const int*)d_in[2];
    const float* ew1   = (const float*)d_in[3];
    const float* eb1   = (const float*)d_in[4];
    const float* ew2   = (const float*)d_in[5];
    const float* eb2   = (const float*)d_in[6];
    const float* gw1   = (const float*)d_in[7];
    const float* gb1   = (const float*)d_in[8];
    const float* gw2   = (const float*)d_in[9];
    const float* gb2   = (const float*)d_in[10];
    const float* gu    = (const float*)d_in[11];
    const float* traw  = (const float*)d_in[12];
    float* out = (float*)d_out;

    const float curv[4] = {-1.0f, 0.0f, 1.0f, -0.5f};

    const int WG = (NN + 7) / 8;
    const int GG = (NN + 127) / 128;

    static cudaStream_t s2 = nullptr, s3 = nullptr;
    static cudaEvent_t evFork, evPrep, evGate, evA0[KEXP], evG1[KEXP];
    if (!s2) {
        cudaStreamCreateWithFlags(&s2, cudaStreamNonBlocking);
        cudaStreamCreateWithFlags(&s3, cudaStreamNonBlocking);
        cudaEventCreateWithFlags(&evFork, cudaEventDisableTiming);
        cudaEventCreateWithFlags(&evPrep, cudaEventDisableTiming);
        cudaEventCreateWithFlags(&evGate, cudaEventDisableTiming);
        for (int e = 0; e < KEXP; e++) {
            cudaEventCreateWithFlags(&evA0[e], cudaEventDisableTiming);
            cudaEventCreateWithFlags(&evG1[e], cudaEventDisableTiming);
        }
    }

    // fork side streams from the capture-origin (default) stream
    cudaEventRecord(evFork, 0);
    cudaStreamWaitEvent(s2, evFork, 0);
    cudaStreamWaitEvent(s3, evFork, 0);

    // main head (slots 1,2,4; slot 3 = s2 prep0)
    k_bias_all<<<KEXP, 128>>>(eb1, 0);                             // 1
    k_norm0<<<WG, 256>>>(x);                                       // 2
    k_prep0<<<(NN + 255) / 256, 256, 0, s2>>>();                   // 3 (s2)
    gemmf<128, 0><<<dim3(GG, KEXP), 256>>>(x, ew1, 16384, NN, 0);  // 4: layer0 GEMM+point

    // s3: layer-1 bias prep (independent; separate bias slot)
    k_bias_all<<<KEXP, 128, 0, s3>>>(eb2, 1);

    // s2: graph prep chain
    k_deg<<<(EE + 255) / 256, 256, 0, s2>>>(col);
    k_dinvsum<<<NB, 256, 0, s2>>>();
    k_scanb<<<1, 256, 0, s2>>>();
    k_off<<<NB, 256, 0, s2>>>();
    k_adj<<<(EE + 255) / 256, 256, 0, s2>>>(row, col);
    cudaEventRecord(evPrep, s2);

    // s2: gate path
    k_gate1<<<(NN + 31) / 32, 256, 0, s2>>>(x, gw1);
    k_gagg1<<<WG, 256, 0, s2>>>(gb1);
    gemmf<32, 2><<<dim3(GG, 1), 256, 0, s2>>>(nullptr, gw2, 0, NN, 0);
    k_gagg2<<<WG, 256, 0, s2>>>(gb2);
    k_pool2<<<dim3(BB, 1), 128, 0, s2>>>(1, batch);
    cudaEventRecord(evGate, s2);

    // main: layer-0 aggs, each feeding a per-expert layer-1 GEMM on s3
    cudaStreamWaitEvent(0, evPrep, 0);
    for (int e = 0; e < KEXP; e++) {
        k_agg<<<WG, 256>>>(e, curv[e], 0);
        cudaEventRecord(evA0[e], 0);
        cudaStreamWaitEvent(s3, evA0[e], 0);
        gemmf<128, 1><<<dim3(GG, 1), 256, 0, s3>>>(nullptr, ew2, 16384, NN, e);
        cudaEventRecord(evG1[e], s3);
    }
    // main: layer-1 aggs (per-expert, gated on that expert's gemm)
    for (int e = 0; e < KEXP; e++) {
        cudaStreamWaitEvent(0, evG1[e], 0);
        k_agg<<<WG, 256>>>(e, curv[e], 1);
    }
    k_pool2<<<dim3(BB, KEXP), 128>>>(0, batch);

    cudaStreamWaitEvent(0, evGate, 0);
    k_finalize<<<BB, 128>>>(gu, traw, out, out_size, batch);
}

// round 17
// speedup vs baseline: 1.5097x; 1.0025x over previous
#include <cuda_runtime.h>
#include <math.h>
#include <stdint.h>

#define NN   50000
#define EE   800000
#define BB   128
#define KEXP 4
#define EPSF 1e-15f
#define NB   ((NN + 255) / 256)   // 196

__constant__ float c_curv[KEXP] = {-1.0f, 0.0f, 1.0f, -0.5f};

// ---------------- scratch (device globals; no runtime allocs) ----------------
__device__ float g_dinv[NN];
__device__ int   g_degcnt[NN];
__device__ int   g_off[NN + 1];
__device__ int   g_cursor[NN];
__device__ int   g_adj[EE];
__device__ int   g_bsum[NB];
__device__ int   g_boff[NB];
__device__ float g_xm[(size_t)KEXP * NN * 128];
__device__ float g_t [(size_t)KEXP * NN * 128];
__device__ float g_xn[(size_t)KEXP * NN];
__device__ float g_s0[(size_t)KEXP * NN];
__device__ float g_gm1[NN * 32];
__device__ float g_g1 [NN * 32];
__device__ float g_gm2[NN * 128];
__device__ float g_gt [NN * 128];
__device__ float g_feat[BB * 512];
__device__ float g_hgate[BB * 128];
__device__ float g_biaspt[2 * KEXP * 128];   // [layer][expert][128]
__device__ float g_bp2[2 * KEXP];

// ---------------- math helpers (all fp32) ----------------
__device__ __forceinline__ float tan_k(float x, float k) {
    if (k > 0.f) { float sk = sqrtf(k);  return tanf(x * sk) / sk; }
    if (k < 0.f) { float sk = sqrtf(-k); return tanhf(x * sk) / sk; }
    return x;
}
__device__ __forceinline__ float artan_k(float x, float k) {
    if (k > 0.f) { float sk = sqrtf(k);  return atanf(x * sk) / sk; }
    if (k < 0.f) {
        float sk = sqrtf(-k);
        float z = fminf(fmaxf(x * sk, -1.0f + 1e-7f), 1.0f - 1e-7f);
        return atanhf(z) / sk;
    }
    return x;
}
__device__ __forceinline__ float warp_sum(float v) {
#pragma unroll
    for (int o = 16; o; o >>= 1) v += __shfl_xor_sync(0xffffffffu, v, o);
    return v;
}
__device__ __forceinline__ float vnorm_w(const float* v) {
    float s = v[0]*v[0] + v[1]*v[1] + v[2]*v[2] + v[3]*v[3];
    return fmaxf(sqrtf(warp_sum(s)), EPSF);
}
__device__ __forceinline__ void project_w(float* v, float k) {
    if (k >= 0.f) return;
    float n = vnorm_w(v);
    float maxn = (1.0f - 1e-5f) * rsqrtf(-k);
    if (n > maxn) {
        float f = maxn / n;
#pragma unroll
        for (int c = 0; c < 4; c++) v[c] *= f;
    }
}
__device__ __forceinline__ void expmap0_w(float* v, float k) {
    float n = vnorm_w(v);
    float s = tan_k(n, k) / n;
#pragma unroll
    for (int c = 0; c < 4; c++) v[c] *= s;
    project_w(v, k);
}
__device__ __forceinline__ void logmap0_w(float* v, float k) {
    float n = vnorm_w(v);
    float s = artan_k(n, k) / n;
#pragma unroll
    for (int c = 0; c < 4; c++) v[c] *= s;
}
__device__ __forceinline__ int lower_bound_batch(const int* __restrict__ b, int val) {
    int lo = 0, hi = NN;
    while (lo < hi) { int mid = (lo + hi) >> 1; if (b[mid] < val) lo = mid + 1; else hi = mid; }
    return lo;
}
__device__ __forceinline__ float bred128(float v, float* sh) {
    v = warp_sum(v);
    int w = threadIdx.x >> 5;
    if ((threadIdx.x & 31) == 0) sh[w] = v;
    __syncthreads();
    float r = sh[0] + sh[1] + sh[2] + sh[3];
    __syncthreads();
    return r;
}

// ---------------- graph prep ----------------
__global__ void k_prep0() {
    int i = blockIdx.x * blockDim.x + threadIdx.x;
    if (i < NN) { g_degcnt[i] = 0; g_cursor[i] = 0; }
}
__global__ void k_deg(const int* __restrict__ col) {
    int e = blockIdx.x * blockDim.x + threadIdx.x;
    if (e < EE) atomicAdd(&g_degcnt[col[e]], 1);
}
__global__ void k_dinvsum() {
    __shared__ int sh[256];
    int t = threadIdx.x;
    int i = blockIdx.x * 256 + t;
    int v = (i < NN) ? g_degcnt[i] : 0;
    if (i < NN) g_dinv[i] = rsqrtf((float)(v + 1));
    sh[t] = v;
    __syncthreads();
#pragma unroll
    for (int o = 128; o; o >>= 1) {
        if (t < o) sh[t] += sh[t + o];
        __syncthreads();
    }
    if (t == 0) g_bsum[blockIdx.x] = sh[0];
}
__global__ void k_scanb() {
    __shared__ int s[256];
    int t = threadIdx.x;
    int v = (t < NB) ? g_bsum[t] : 0;
    s[t] = v;
    __syncthreads();
#pragma unroll
    for (int o = 1; o < 256; o <<= 1) {
        int x = (t >= o) ? s[t - o] : 0;
        __syncthreads();
        s[t] += x;
        __syncthreads();
    }
    if (t < NB) g_boff[t] = s[t] - v;
    if (t == 255) g_off[NN] = s[255];
}
__global__ void k_off() {
    __shared__ int s[256];
    int t = threadIdx.x;
    int i = blockIdx.x * 256 + t;
    int v = (i < NN) ? g_degcnt[i] : 0;
    s[t] = v;
    __syncthreads();
#pragma unroll
    for (int o = 1; o < 256; o <<= 1) {
        int x = (t >= o) ? s[t - o] : 0;
        __syncthreads();
        s[t] += x;
        __syncthreads();
    }
    if (i < NN) g_off[i] = g_boff[blockIdx.x] + s[t] - v;
}
__global__ void k_adj(const int* __restrict__ row, const int* __restrict__ col) {
    int e = blockIdx.x * blockDim.x + threadIdx.x;
    if (e < EE) {
        int d = col[e];
        int p = g_off[d] + atomicAdd(&g_cursor[d], 1);
        g_adj[p] = row[e];
    }
}

// ---------------- layer-0 prep: per-node expmap0 scale + norm for all experts --------
__global__ void k_norm0(const float* __restrict__ x) {
    int node = blockIdx.x * 8 + (threadIdx.x >> 5);
    if (node >= NN) return;
    int lane = threadIdx.x & 31;
    float4 xv = ((const float4*)(x + (size_t)node * 128))[lane];
    float s2 = xv.x*xv.x + xv.y*xv.y + xv.z*xv.z + xv.w*xv.w;
    float n = fmaxf(sqrtf(warp_sum(s2)), EPSF);
    if (lane == 0) {
#pragma unroll
        for (int e = 0; e < KEXP; e++) {
            float k = c_curv[e];
            float tk = tan_k(n, k);
            float s = tk / n;
            float vn = fabsf(tk);
            if (k < 0.f) {
                float maxn = (1.0f - 1e-5f) * rsqrtf(-k);
                if (vn > maxn) { s *= maxn / vn; vn = maxn; }
            }
            g_s0[(size_t)e * NN + node] = s;
            g_xn[(size_t)e * NN + node] = fmaxf(vn, EPSF);
        }
    }
}

__global__ void k_bias_all(const float* __restrict__ bsrc, int layer) { // grid=KEXP
    __shared__ float sh[4];
    int e = blockIdx.x;
    float k = c_curv[e];
    int t = threadIdx.x;
    float v = bsrc[e * 128 + t];
    float n2 = bred128(v * v, sh);
    float n = fmaxf(sqrtf(n2), EPSF);
    float p = (tan_k(n, k) / n) * v;
    if (k < 0.f) {
        float p2 = bred128(p * p, sh);
        float pn = fmaxf(sqrtf(p2), EPSF);
        float maxn = (1.0f - 1e-5f) * rsqrtf(-k);
        if (pn > maxn) p *= maxn / pn;
    }
    float p2f = bred128(p * p, sh);
    g_biaspt[(layer * KEXP + e) * 128 + t] = p;
    if (t == 0) g_bp2[layer * KEXP + e] = p2f;
}

// gather-aggregate (CSR) + expmap0 [+ fused logmap0 final layer]: g_t[e] -> g_xm[e]
__global__ void k_agg(int e, float k, int fuseLog) {
    int d = blockIdx.x * 8 + (threadIdx.x >> 5);
    if (d >= NN) return;
    int lane = threadIdx.x & 31;
    const float* __restrict__ t = g_t + (size_t)e * NN * 128;
    float dd = g_dinv[d];
    float4 sv4 = ((const float4*)(t + (size_t)d * 128))[lane];
    float sw = dd * dd;
    float a0 = sw * sv4.x, a1 = sw * sv4.y, a2 = sw * sv4.z, a3 = sw * sv4.w;
    int p0 = g_off[d], p1 = g_off[d + 1];
    for (int p = p0; p < p1; p += 32) {
        int cnt = min(32, p1 - p);
        int sidx = 0; float wv = 0.f;
        if (p + lane < p1) { sidx = g_adj[p + lane]; wv = dd * g_dinv[sidx]; }
        int q = 0;
        for (; q + 4 <= cnt; q += 4) {
            int s0 = __shfl_sync(0xffffffffu, sidx, q);
            int s1 = __shfl_sync(0xffffffffu, sidx, q + 1);
            int s2 = __shfl_sync(0xffffffffu, sidx, q + 2);
            int s3 = __shfl_sync(0xffffffffu, sidx, q + 3);
            float w0 = __shfl_sync(0xffffffffu, wv, q);
            float w1 = __shfl_sync(0xffffffffu, wv, q + 1);
            float w2 = __shfl_sync(0xffffffffu, wv, q + 2);
            float w3 = __shfl_sync(0xffffffffu, wv, q + 3);
            float4 n0 = ((const float4*)(t + (size_t)s0 * 128))[lane];
            float4 n1 = ((const float4*)(t + (size_t)s1 * 128))[lane];
            float4 n2 = ((const float4*)(t + (size_t)s2 * 128))[lane];
            float4 n3 = ((const float4*)(t + (size_t)s3 * 128))[lane];
            a0 = fmaf(w0, n0.x, a0); a1 = fmaf(w0, n0.y, a1);
            a2 = fmaf(w0, n0.z, a2); a3 = fmaf(w0, n0.w, a3);
            a0 = fmaf(w1, n1.x, a0); a1 = fmaf(w1, n1.y, a1);
            a2 = fmaf(w1, n1.z, a2); a3 = fmaf(w1, n1.w, a3);
            a0 = fmaf(w2, n2.x, a0); a1 = fmaf(w2, n2.y, a1);
            a2 = fmaf(w2, n2.z, a2); a3 = fmaf(w2, n2.w, a3);
            a0 = fmaf(w3, n3.x, a0); a1 = fmaf(w3, n3.y, a1);
            a2 = fmaf(w3, n3.z, a2); a3 = fmaf(w3, n3.w, a3);
        }
        for (; q < cnt; q++) {
            int   s = __shfl_sync(0xffffffffu, sidx, q);
            float w = __shfl_sync(0xffffffffu, wv, q);
            float4 nv = ((const float4*)(t + (size_t)s * 128))[lane];
            a0 = fmaf(w, nv.x, a0); a1 = fmaf(w, nv.y, a1);
            a2 = fmaf(w, nv.z, a2); a3 = fmaf(w, nv.w, a3);
        }
    }
    float v[4] = {a0, a1, a2, a3};
    expmap0_w(v, k);
    if (fuseLog) {
        logmap0_w(v, k);
    } else {
        float nv = vnorm_w(v);
        if (lane == 0) g_xn[(size_t)e * NN + d] = nv;
    }
    ((float4*)(g_xm + ((size_t)e * NN + d) * 128))[lane] = make_float4(v[0], v[1], v[2], v[3]);
}

// ---------------- GEMM (+ fused Mobius point epilogue) ----------------
// Quarter-tile software pipeline: prefetch next 8-k quarter (global->regs)
// before computing the current quarter; 1 barrier per quarter. Identical
// FMA order per output element (kk ascending 0..KD-1).
// MODE 0: layer0 — A = x (shared), row scale c=g_s0[e][node], OUT=g_t[e], bias layer 0
// MODE 1: layer1 — A = g_xm[e], c=1, OUT=g_t[e], bias layer 1
// MODE 2: gate   — A = g_g1, plain C to g_gm2
template<int KD, int MODE>
__global__ void __launch_bounds__(256, 2)
gemmf(const float* __restrict__ Xin, const float* __restrict__ W0,
      int wOfs, int n, int eBase) {
    const float* __restrict__ A;
    float* __restrict__ OUT;
    int lda;
    int eIdx = eBase + blockIdx.y;
    if (MODE == 0) {
        A = Xin; OUT = g_t + (size_t)eIdx * NN * 128; lda = 128;
    } else if (MODE == 1) {
        size_t eo = (size_t)eIdx * NN * 128;
        A = g_xm + eo; OUT = g_t + eo; lda = 128;
    } else {
        A = g_g1; OUT = g_gm2; lda = 32;
    }
    const float* __restrict__ W = W0 + (size_t)eIdx * wOfs;
    __shared__ __align__(16) float As[32][132];
    __shared__ __align__(16) float Bs[32][132];
    __shared__ float red2[128][17];
    __shared__ float redd[128][17];
    __shared__ float reda[128][17];
    __shared__ float2 abArr[128];
    int tid = threadIdx.x;
    int tx = tid & 15, ty = tid >> 4;
    int node0 = blockIdx.x * 128;

    // quarter-load mapping: each thread owns A row mQ and W row mQ,
    // covering 4 consecutive k at kQ within the 8-wide quarter.
    const int mQ = tid >> 1;          // 0..127
    const int kQ = (tid & 1) * 4;     // 0 or 4
    const bool mOk = (node0 + mQ < n);
    float4 va, vb;

    float acc[8][8];
#pragma unroll
    for (int m = 0; m < 8; m++)
#pragma unroll
        for (int j = 0; j < 8; j++) acc[m][j] = 0.f;

    // prologue: load + store quarter 0 (global k 0..7)
    {
        va = make_float4(0.f, 0.f, 0.f, 0.f);
        if (mOk) va = *(const float4*)(A + (size_t)(node0 + mQ) * lda + kQ);
        vb = *(const float4*)(W + (size_t)mQ * KD + kQ);
        int r = kQ;
        As[r+0][mQ]=va.x; As[r+1][mQ]=va.y; As[r+2][mQ]=va.z; As[r+3][mQ]=va.w;
        Bs[r+0][mQ]=vb.x; Bs[r+1][mQ]=vb.y; Bs[r+2][mQ]=vb.z; Bs[r+3][mQ]=vb.w;
    }
    __syncthreads();

    const int NIT = KD / 32;
    for (int it = 0; it < NIT; it++) {
#pragma unroll
        for (int q = 0; q < 4; q++) {
            // prefetch next quarter into regs (hidden under compute below)
            int nIt = (q < 3) ? it : it + 1;
            int nQr = (q + 1) & 3;
            bool haveNext = (nIt < NIT);
            if (haveNext) {
                int gk = nIt * 32 + nQr * 8 + kQ;
                va = make_float4(0.f, 0.f, 0.f, 0.f);
                if (mOk) va = *(const float4*)(A + (size_t)(node0 + mQ) * lda + gk);
                vb = *(const float4*)(W + (size_t)mQ * KD + gk);
            }
            // compute the current quarter (kk = q*8 .. q*8+7)
#pragma unroll
            for (int kk2 = 0; kk2 < 8; kk2++) {
                const int kk = q * 8 + kk2;
                float4 a0 = *(const float4*)&As[kk][ty * 4];
                float4 a1 = *(const float4*)&As[kk][64 + ty * 4];
                float4 b0 = *(const float4*)&Bs[kk][tx * 4];
                float4 b1 = *(const float4*)&Bs[kk][64 + tx * 4];
                float a[8] = {a0.x, a0.y, a0.z, a0.w, a1.x, a1.y, a1.z, a1.w};
                float b[8] = {b0.x, b0.y, b0.z, b0.w, b1.x, b1.y, b1.z, b1.w};
#pragma unroll
                for (int m = 0; m < 8; m++)
#pragma unroll
                    for (int j = 0; j < 8; j++) acc[m][j] = fmaf(a[m], b[j], acc[m][j]);
            }
            // store prefetched quarter into its (disjoint) region, then barrier
            if (haveNext) {
                int r = nQr * 8 + kQ;
                As[r+0][mQ]=va.x; As[r+1][mQ]=va.y; As[r+2][mQ]=va.z; As[r+3][mQ]=va.w;
                Bs[r+0][mQ]=vb.x; Bs[r+1][mQ]=vb.y; Bs[r+2][mQ]=vb.z; Bs[r+3][mQ]=vb.w;
            }
            __syncthreads();
        }
    }

    if (MODE == 2) {
#pragma unroll
        for (int m = 0; m < 8; m++) {
            int row = node0 + ((m < 4) ? (ty * 4 + m) : (64 + ty * 4 + m - 4));
            if (row < n) {
                *(float4*)(OUT + (size_t)row * 128 + tx * 4) =
                    make_float4(acc[m][0], acc[m][1], acc[m][2], acc[m][3]);
                *(float4*)(OUT + (size_t)row * 128 + 64 + tx * 4) =
                    make_float4(acc[m][4], acc[m][5], acc[m][6], acc[m][7]);
            }
        }
        return;
    }

    // ---- fused point epilogue (bias loaded here, outside the mainloop) ----
    const int bofs = (MODE == 0) ? 0 : KEXP;
    float bpv[8];
    {
        float4 b0 = *(const float4*)(g_biaspt + (bofs + eIdx) * 128 + tx * 4);
        float4 b1 = *(const float4*)(g_biaspt + (bofs + eIdx) * 128 + 64 + tx * 4);
        bpv[0]=b0.x; bpv[1]=b0.y; bpv[2]=b0.z; bpv[3]=b0.w;
        bpv[4]=b1.x; bpv[5]=b1.y; bpv[6]=b1.z; bpv[7]=b1.w;
    }
    float kv = c_curv[eIdx];
#pragma unroll
    for (int m = 0; m < 8; m++) {
        int rloc = (m < 4) ? (ty * 4 + m) : (64 + ty * 4 + m - 4);
        float s2 = 0.f, sd = 0.f, sa = 0.f;
#pragma unroll
        for (int j = 0; j < 8; j++) {
            float v = acc[m][j];
            s2 = fmaf(v, v, s2); sd = fmaf(v, bpv[j], sd); sa += fabsf(v);
        }
        red2[rloc][tx] = s2; redd[rloc][tx] = sd; reda[rloc][tx] = sa;
    }
    __syncthreads();
    if (tid < 128) {
        int node = node0 + tid;
        if (node < n) {
            float S2 = 0.f, SD = 0.f, SA = 0.f;
#pragma unroll
            for (int i = 0; i < 16; i++) {
                S2 += red2[tid][i]; SD += redd[tid][i]; SA += reda[tid][i];
            }
            float c = 1.f;
            if (MODE == 0) c = g_s0[(size_t)eIdx * NN + node];
            S2 *= c * c; SD *= c; SA *= fabsf(c);
            float alpha, beta;
            if (kv == 0.f) {
                alpha = 1.f; beta = 1.f;
            } else {
                float bp2 = g_bp2[bofs + eIdx];
                float mxn = fmaxf(sqrtf(S2), EPSF);
                float xn  = g_xn[(size_t)eIdx * NN + node];
                float s1 = tan_k(mxn / xn * artan_k(xn, kv), kv) / mxn;
                if (SA == 0.f) s1 = 0.f;
                if (kv < 0.f) {
                    float maxn = (1.0f - 1e-5f) * rsqrtf(-kv);
                    float hn = fmaxf(fabsf(s1) * mxn, EPSF);
                    if (hn > maxn) s1 *= maxn / hn;
                }
                float h2 = s1 * s1 * S2;
                float xy = s1 * SD;
                float num_h = 1.f - 2.f * kv * xy - kv * bp2;
                float num_b = 1.f + kv * h2;
                float den = fmaxf(1.f - 2.f * kv * xy + kv * kv * h2 * bp2, 1e-15f);
                float a1f = num_h * s1 / den;
                float b1f = num_b / den;
                float an2 = fmaxf(a1f * a1f * S2 + 2.f * a1f * b1f * SD + b1f * b1f * bp2, 0.f);
                float an = fmaxf(sqrtf(an2), EPSF);
                float cf2 = 1.f;
                if (kv < 0.f) {
                    float maxn = (1.0f - 1e-5f) * rsqrtf(-kv);
                    if (an > maxn) cf2 = maxn / an;
                }
                float np = fmaxf(an * cf2, EPSF);
                float lg = artan_k(np, kv) / np;
                alpha = lg * cf2 * a1f;
                beta  = lg * cf2 * b1f;
            }
            abArr[tid] = make_float2(alpha * c, beta);
        }
    }
    __syncthreads();
#pragma unroll
    for (int m = 0; m < 8; m++) {
        int rloc = (m < 4) ? (ty * 4 + m) : (64 + ty * 4 + m - 4);
        int row = node0 + rloc;
        if (row < n) {
            float2 ab = abArr[rloc];
            float o[8];
#pragma unroll
            for (int j = 0; j < 8; j++) o[j] = fmaf(ab.x, acc[m][j], ab.y * bpv[j]);
            *(float4*)(OUT + (size_t)row * 128 + tx * 4) =
                make_float4(o[0], o[1], o[2], o[3]);
            *(float4*)(OUT + (size_t)row * 128 + 64 + tx * 4) =
                make_float4(o[4], o[5], o[6], o[7]);
        }
    }
}

// ---------------- gate ----------------
__global__ void k_gate1(const float* __restrict__ x, const float* __restrict__ gw1) {
    __shared__ float wT[128 * 33];
    int tid = threadIdx.x;
    for (int l = tid; l < 4096; l += 256) {
        int j = l >> 7, i = l & 127;
        wT[i * 33 + j] = gw1[l];
    }
    __syncthreads();
    int warp = tid >> 5, lane = tid & 31;
    for (int rep = 0; rep < 4; rep++) {
        int node = blockIdx.x * 32 + rep * 8 + warp;
        if (node < NN) {
            float xv[4];
#pragma unroll
            for (int c = 0; c < 4; c++) xv[c] = x[node * 128 + c * 32 + lane];
            float accv = 0.f;
#pragma unroll
            for (int i = 0; i < 128; i++) {
                float xi = __shfl_sync(0xffffffffu, xv[i >> 5], i & 31);
                accv = fmaf(xi, wT[i * 33 + lane], accv);
            }
            g_gm1[node * 32 + lane] = accv;
        }
    }
}
__global__ void k_gagg1(const float* __restrict__ gb1) {
    int d = blockIdx.x * 8 + (threadIdx.x >> 5);
    if (d >= NN) return;
    int lane = threadIdx.x & 31;
    float dd = g_dinv[d];
    float acc = dd * dd * g_gm1[d * 32 + lane];
    int p0 = g_off[d], p1 = g_off[d + 1];
    for (int p = p0; p < p1; p += 32) {
        int cnt = min(32, p1 - p);
        int sidx = 0; float wv = 0.f;
        if (p + lane < p1) { sidx = g_adj[p + lane]; wv = dd * g_dinv[sidx]; }
        for (int q = 0; q < cnt; q++) {
            int   s = __shfl_sync(0xffffffffu, sidx, q);
            float w = __shfl_sync(0xffffffffu, wv, q);
            acc += w * g_gm1[s * 32 + lane];
        }
    }
    g_g1[d * 32 + lane] = fmaxf(acc + gb1[lane], 0.f);
}
__global__ void k_gagg2(const float* __restrict__ gb2) {
    int d = blockIdx.x * 8 + (threadIdx.x >> 5);
    if (d >= NN) return;
    int lane = threadIdx.x & 31;
    float dd = g_dinv[d];
    float4 sv4 = ((const float4*)(g_gm2 + (size_t)d * 128))[lane];
    float sw = dd * dd;
    float a0 = sw * sv4.x, a1 = sw * sv4.y, a2 = sw * sv4.z, a3 = sw * sv4.w;
    int p0 = g_off[d], p1 = g_off[d + 1];
    for (int p = p0; p < p1; p += 32) {
        int cnt = min(32, p1 - p);
        int sidx = 0; float wv = 0.f;
        if (p + lane < p1) { sidx = g_adj[p + lane]; wv = dd * g_dinv[sidx]; }
        int q = 0;
        for (; q + 4 <= cnt; q += 4) {
            int s0 = __shfl_sync(0xffffffffu, sidx, q);
            int s1 = __shfl_sync(0xffffffffu, sidx, q + 1);
            int s2 = __shfl_sync(0xffffffffu, sidx, q + 2);
            int s3 = __shfl_sync(0xffffffffu, sidx, q + 3);
            float w0 = __shfl_sync(0xffffffffu, wv, q);
            float w1 = __shfl_sync(0xffffffffu, wv, q + 1);
            float w2 = __shfl_sync(0xffffffffu, wv, q + 2);
            float w3 = __shfl_sync(0xffffffffu, wv, q + 3);
            float4 n0 = ((const float4*)(g_gm2 + (size_t)s0 * 128))[lane];
            float4 n1 = ((const float4*)(g_gm2 + (size_t)s1 * 128))[lane];
            float4 n2 = ((const float4*)(g_gm2 + (size_t)s2 * 128))[lane];
            float4 n3 = ((const float4*)(g_gm2 + (size_t)s3 * 128))[lane];
            a0 = fmaf(w0, n0.x, a0); a1 = fmaf(w0, n0.y, a1);
            a2 = fmaf(w0, n0.z, a2); a3 = fmaf(w0, n0.w, a3);
            a0 = fmaf(w1, n1.x, a0); a1 = fmaf(w1, n1.y, a1);
            a2 = fmaf(w1, n1.z, a2); a3 = fmaf(w1, n1.w, a3);
            a0 = fmaf(w2, n2.x, a0); a1 = fmaf(w2, n2.y, a1);
            a2 = fmaf(w2, n2.z, a2); a3 = fmaf(w2, n2.w, a3);
            a0 = fmaf(w3, n3.x, a0); a1 = fmaf(w3, n3.y, a1);
            a2 = fmaf(w3, n3.z, a2); a3 = fmaf(w3, n3.w, a3);
        }
        for (; q < cnt; q++) {
            int   s = __shfl_sync(0xffffffffu, sidx, q);
            float w = __shfl_sync(0xffffffffu, wv, q);
            float4 nv = ((const float4*)(g_gm2 + (size_t)s * 128))[lane];
            a0 = fmaf(w, nv.x, a0); a1 = fmaf(w, nv.y, a1);
            a2 = fmaf(w, nv.z, a2); a3 = fmaf(w, nv.w, a3);
        }
    }
    float4 bv = ((const float4*)gb2)[lane];
    ((float4*)(g_gt + (size_t)d * 128))[lane] = make_float4(
        fmaxf(a0 + bv.x, 0.f), fmaxf(a1 + bv.y, 0.f),
        fmaxf(a2 + bv.z, 0.f), fmaxf(a3 + bv.w, 0.f));
}

// ---------------- pooling ----------------
__global__ void k_pool2(int sel, const int* __restrict__ batch) {
    int b = blockIdx.x, e = blockIdx.y, j = threadIdx.x;
    const float* __restrict__ src = (sel == 0) ? (g_xm + (size_t)e * NN * 128) : g_gt;
    int s = lower_bound_batch(batch, b);
    int ee = lower_bound_batch(batch, b + 1);
    float a0 = 0.f, a1 = 0.f, a2 = 0.f, a3 = 0.f;
    int nd = s;
    for (; nd + 4 <= ee; nd += 4) {
        a0 += src[(size_t)(nd + 0) * 128 + j];
        a1 += src[(size_t)(nd + 1) * 128 + j];
        a2 += src[(size_t)(nd + 2) * 128 + j];
        a3 += src[(size_t)(nd + 3) * 128 + j];
    }
    for (; nd < ee; ++nd) a0 += src[(size_t)nd * 128 + j];
    float sum = (a0 + a1) + (a2 + a3);
    if (sel == 0) g_feat[b * 512 + e * 128 + j] = sum;
    else          g_hgate[b * 128 + j] = sum;
}

// ---------------- finalize ----------------
__global__ void k_finalize(const float* __restrict__ gate_u, const float* __restrict__ tau_raw,
                           float* __restrict__ out, int out_size, const int* __restrict__ batch) {
    __shared__ float sh[4];
    int b = blockIdx.x, j = threadIdx.x;
    int s = lower_bound_batch(batch, b);
    int e = lower_bound_batch(batch, b + 1);
    float c = fmaxf((float)(e - s), 1.0f);
    float hg = g_hgate[b * 128 + j] / c;
    float hn2 = bred128(hg * hg, sh);
    const float curv[4] = {-1.0f, 0.0f, 1.0f, -0.5f};
    float dv[4], tauv[4];
    for (int i = 0; i < 4; i++) {
        float k = curv[i];
        float zn = fmaxf(sqrtf(hn2), EPSF);
        float zk = (tan_k(zn, k) / zn) * hg;
        if (k < 0.f) {
            float z2 = bred128(zk * zk, sh);
            float n = fmaxf(sqrtf(z2), EPSF);
            float maxn = (1.0f - 1e-5f) * rsqrtf(-k);
            if (n > maxn) zk *= maxn / n;
        }
        float u = gate_u[i * 128 + j];
        float un2 = bred128(u * u, sh);
        float un = fmaxf(sqrtf(un2), EPSF);
        float yk = (tan_k(un, k) / un) * u;
        if (k < 0.f) {
            float y2p = bred128(yk * yk, sh);
            float n = fmaxf(sqrtf(y2p), EPSF);
            float maxn = (1.0f - 1e-5f) * rsqrtf(-k);
            if (n > maxn) yk *= maxn / n;
        }
        float xe = -zk;
        float x2 = bred128(xe * xe, sh);
        float y2 = bred128(yk * yk, sh);
        float xy = bred128(xe * yk, sh);
        float nh = 1.f - 2.f * k * xy - k * y2;
        float nb = 1.f + k * x2;
        float den = fmaxf(1.f - 2.f * k * xy + k * k * x2 * y2, 1e-15f);
        float m = (nh * xe + nb * yk) / den;
        if (k < 0.f) {
            float m2p = bred128(m * m, sh);
            float n = fmaxf(sqrtf(m2p), EPSF);
            float maxn = (1.0f - 1e-5f) * rsqrtf(-k);
            if (n > maxn) m *= maxn / n;
        }
        float m2 = bred128(m * m, sh);
        dv[i] = 2.0f * artan_k(fmaxf(sqrtf(m2), EPSF), k);
        float tr = tau_raw[i];
        float sp = (tr > 20.f) ? tr : log1pf(expf(tr));
        tauv[i] = fminf(fmaxf(sp + 0.05f, 0.05f), 10.0f);
    }
    float l[4], mxl = -1e30f;
#pragma unroll
    for (int i = 0; i < 4; i++) { l[i] = -dv[i] / tauv[i]; mxl = fmaxf(mxl, l[i]); }
    float sum = 0.f;
#pragma unroll
    for (int i = 0; i < 4; i++) { l[i] = expf(l[i] - mxl); sum += l[i]; }
    float w[4];
#pragma unroll
    for (int i = 0; i < 4; i++) w[i] = l[i] / sum;
#pragma unroll
    for (int i = 0; i < 4; i++) {
        int idx = b * 512 + i * 128 + j;
        out[idx] = (g_feat[idx] / c) * w[i];
    }
    if (out_size >= 66564) {
        if (j < 4) {
            out[65536 + b * 4 + j] = w[j];
            out[66048 + b * 4 + j] = dv[j];
            if (b == 0) out[66560 + j] = tauv[j];
        }
    }
}

// ---------------- launch (3 streams: expert aggs | prep+gate | layer-1 gemms) --------
extern "C" void kernel_launch(void* const* d_in, const int* in_sizes, int n_in,
                              void* d_out, int out_size) {
    const float* x     = (const float*)d_in[0];
    const int*   ei    = (const int*)d_in[1];
    const int*   row   = ei;
    const int*   col   = ei + EE;
    const int*   batch = (const int*)d_in[2];
    const float* ew1   = (const float*)d_in[3];
    const float* eb1   = (const float*)d_in[4];
    const float* ew2   = (const float*)d_in[5];
    const float* eb2   = (const float*)d_in[6];
    const float* gw1   = (const float*)d_in[7];
    const float* gb1   = (const float*)d_in[8];
    const float* gw2   = (const float*)d_in[9];
    const float* gb2   = (const float*)d_in[10];
    const float* gu    = (const float*)d_in[11];
    const float* traw  = (const float*)d_in[12];
    float* out = (float*)d_out;

    const float curv[4] = {-1.0f, 0.0f, 1.0f, -0.5f};

    const int WG = (NN + 7) / 8;
    const int GG = (NN + 127) / 128;

    static cudaStream_t s2 = nullptr, s3 = nullptr;
    static cudaEvent_t evFork, evPrep, evGate, evA0[KEXP], evG1[KEXP];
    if (!s2) {
        cudaStreamCreateWithFlags(&s2, cudaStreamNonBlocking);
        cudaStreamCreateWithFlags(&s3, cudaStreamNonBlocking);
        cudaEventCreateWithFlags(&evFork, cudaEventDisableTiming);
        cudaEventCreateWithFlags(&evPrep, cudaEventDisableTiming);
        cudaEventCreateWithFlags(&evGate, cudaEventDisableTiming);
        for (int e = 0; e < KEXP; e++) {
            cudaEventCreateWithFlags(&evA0[e], cudaEventDisableTiming);
            cudaEventCreateWithFlags(&evG1[e], cudaEventDisableTiming);
        }
    }

    // fork side streams from the capture-origin (default) stream
    cudaEventRecord(evFork, 0);
    cudaStreamWaitEvent(s2, evFork, 0);
    cudaStreamWaitEvent(s3, evFork, 0);

    // main head (slots 1,2,4; slot 3 = s2 prep0)
    k_bias_all<<<KEXP, 128>>>(eb1, 0);                             // 1
    k_norm0<<<WG, 256>>>(x);                                       // 2
    k_prep0<<<(NN + 255) / 256, 256, 0, s2>>>();                   // 3 (s2)
    gemmf<128, 0><<<dim3(GG, KEXP), 256>>>(x, ew1, 16384, NN, 0);  // 4: layer0 GEMM+point

    // s3: layer-1 bias prep (independent; separate bias slot)
    k_bias_all<<<KEXP, 128, 0, s3>>>(eb2, 1);

    // s2: graph prep chain
    k_deg<<<(EE + 255) / 256, 256, 0, s2>>>(col);
    k_dinvsum<<<NB, 256, 0, s2>>>();
    k_scanb<<<1, 256, 0, s2>>>();
    k_off<<<NB, 256, 0, s2>>>();
    k_adj<<<(EE + 255) / 256, 256, 0, s2>>>(row, col);
    cudaEventRecord(evPrep, s2);

    // s2: gate path
    k_gate1<<<(NN + 31) / 32, 256, 0, s2>>>(x, gw1);
    k_gagg1<<<WG, 256, 0, s2>>>(gb1);
    gemmf<32, 2><<<dim3(GG, 1), 256, 0, s2>>>(nullptr, gw2, 0, NN, 0);
    k_gagg2<<<WG, 256, 0, s2>>>(gb2);
    k_pool2<<<dim3(BB, 1), 128, 0, s2>>>(1, batch);
    cudaEventRecord(evGate, s2);

    // main: layer-0 aggs, each feeding a per-expert layer-1 GEMM on s3
    cudaStreamWaitEvent(0, evPrep, 0);
    for (int e = 0; e < KEXP; e++) {
        k_agg<<<WG, 256>>>(e, curv[e], 0);
        cudaEventRecord(evA0[e], 0);
        cudaStreamWaitEvent(s3, evA0[e], 0);
        gemmf<128, 1><<<dim3(GG, 1), 256, 0, s3>>>(nullptr, ew2, 16384, NN, e);
        cudaEventRecord(evG1[e], s3);
    }
    // main: layer-1 aggs (per-expert, gated on that expert's gemm)
    for (int e = 0; e < KEXP; e++) {
        cudaStreamWaitEvent(0, evG1[e], 0);
        k_agg<<<WG, 256>>>(e, curv[e], 1);
    }
    k_pool2<<<dim3(BB, KEXP), 128>>>(0, batch);

    cudaStreamWaitEvent(0, evGate, 0);
    k_finalize<<<BB, 128>>>(gu, traw, out, out_size, batch);
}